// round 11
// baseline (speedup 1.0000x reference)
#include <cuda_runtime.h>
#include <cuda_bf16.h>
#include <math.h>
#include <stdint.h>

// ---------------- problem constants ----------------
#define IN_DIM   128
#define E_DIM    32
#define CAT_DIM  160
#define OUT_DIM  128
#define TD       32
#define H_HEADS  8
#define HS       16
#define R_TYPES  8
#define T_TYPES  4
#define LN_EPS   1e-5f
#define E_MAX    100000
#define M_MAX    10000
#define TILE_E   128
#define TILE_M   64

typedef unsigned long long ull;

// ---------------- device scratch ----------------
__device__ __nv_bfloat16 g_wq_hi[(size_t)R_TYPES * OUT_DIM * IN_DIM];
__device__ __nv_bfloat16 g_wq_lo[(size_t)R_TYPES * OUT_DIM * IN_DIM];
__device__ __nv_bfloat16 g_wk_hi[(size_t)R_TYPES * OUT_DIM * CAT_DIM];
__device__ __nv_bfloat16 g_wk_lo[(size_t)R_TYPES * OUT_DIM * CAT_DIM];
__device__ __nv_bfloat16 g_wv_hi[(size_t)R_TYPES * OUT_DIM * CAT_DIM];
__device__ __nv_bfloat16 g_wv_lo[(size_t)R_TYPES * OUT_DIM * CAT_DIM];

__device__ float    g_q[(size_t)E_MAX * OUT_DIM];
__device__ float    g_k[(size_t)E_MAX * OUT_DIM];
__device__ float    g_v[(size_t)E_MAX * OUT_DIM];
__device__ float    g_a[(size_t)E_MAX * H_HEADS];
__device__ float    g_hacc[(size_t)M_MAX * OUT_DIM];

// fixed-stride type buckets (cursor == count after scatter)
__device__ int      g_cur[R_TYPES];
__device__ int      g_order[(size_t)R_TYPES * E_MAX];
__device__ int      g_ncur[T_TYPES];
__device__ int      g_norder[(size_t)T_TYPES * M_MAX];
// dst-sorted edge index (contiguous buckets)
__device__ int      g_dhist[M_MAX], g_doff[M_MAX], g_dcur[M_MAX];
__device__ int      g_dorder[E_MAX];

// ---------------- f32x2 packed-FMA helpers (k_out) ----------------
__device__ __forceinline__ ull fma2(ull a, ull b, ull c) {
    ull d;
    asm("fma.rn.f32x2 %0, %1, %2, %3;" : "=l"(d) : "l"(a), "l"(b), "l"(c));
    return d;
}
__device__ __forceinline__ ull dup2(float x) {
    ull d; asm("mov.b64 %0, {%1, %1};" : "=l"(d) : "f"(x)); return d;
}
__device__ __forceinline__ float2 unpk(ull v) {
    float2 f; asm("mov.b64 {%0, %1}, %2;" : "=f"(f.x), "=f"(f.y) : "l"(v)); return f;
}

// ---------------- mma.sync helpers ----------------
__device__ __forceinline__ uint32_t smem_u32(const void* p) {
    uint32_t a;
    asm("{ .reg .u64 t; cvta.to.shared.u64 t, %1; cvt.u32.u64 %0, t; }"
        : "=r"(a) : "l"(p));
    return a;
}
__device__ __forceinline__ void ldsm4(uint32_t& r0, uint32_t& r1, uint32_t& r2,
                                      uint32_t& r3, uint32_t addr) {
    asm volatile("ldmatrix.sync.aligned.m8n8.x4.shared.b16 {%0,%1,%2,%3}, [%4];"
                 : "=r"(r0), "=r"(r1), "=r"(r2), "=r"(r3) : "r"(addr));
}
__device__ __forceinline__ void mma16816(float* d, uint32_t a0, uint32_t a1,
                                         uint32_t a2, uint32_t a3,
                                         uint32_t b0, uint32_t b1) {
    asm volatile(
        "mma.sync.aligned.m16n8k16.row.col.f32.bf16.bf16.f32 "
        "{%0,%1,%2,%3}, {%4,%5,%6,%7}, {%8,%9}, {%0,%1,%2,%3};"
        : "+f"(d[0]), "+f"(d[1]), "+f"(d[2]), "+f"(d[3])
        : "r"(a0), "r"(a1), "r"(a2), "r"(a3), "r"(b0), "r"(b1));
}

// ---------------- reset ----------------
__global__ void k_reset(int M) {
    int t = blockIdx.x * blockDim.x + threadIdx.x;
    if (t < M)       { g_dhist[t] = 0; g_dcur[t] = 0; }
    if (t < R_TYPES) g_cur[t] = 0;
    if (t < T_TYPES) g_ncur[t] = 0;
}

// ---------------- scatter: etype buckets, ntype buckets, dst histogram ----
__global__ void k_scatter_all(const int* __restrict__ etype,
                              const int* __restrict__ ntype,
                              const int* __restrict__ dst_idx,
                              int E, int M) {
    int t = blockIdx.x * blockDim.x + threadIdx.x;
    int lane = threadIdx.x & 31;
    unsigned actE = __ballot_sync(0xffffffffu, t < E);
    if (t < E) {
        int r = etype[t];
        unsigned m = __match_any_sync(actE, r);
        int leader = __ffs(m) - 1;
        int rank = __popc(m & ((1u << lane) - 1));
        int base = 0;
        if (lane == leader) base = atomicAdd(&g_cur[r], __popc(m));
        base = __shfl_sync(actE, base, leader);
        g_order[(size_t)r * E_MAX + base + rank] = t;
        atomicAdd(&g_dhist[dst_idx[t]], 1);
    }
    unsigned actM = __ballot_sync(0xffffffffu, t < M);
    if (t < M) {
        int r = ntype[t];
        unsigned m = __match_any_sync(actM, r);
        int leader = __ffs(m) - 1;
        int rank = __popc(m & ((1u << lane) - 1));
        int base = 0;
        if (lane == leader) base = atomicAdd(&g_ncur[r], __popc(m));
        base = __shfl_sync(actM, base, leader);
        g_norder[(size_t)r * M_MAX + base + rank] = t;
    }
}

// ---------------- single-block exclusive scan of g_dhist -> g_doff -------
__global__ void __launch_bounds__(1024, 1) k_scan_dst(int M) {
    const int tid = threadIdx.x;
    const int per = (M + 1023) / 1024;
    const int start = tid * per;
    const int end = min(start + per, M);
    int local = 0;
    for (int i = start; i < end; i++) local += g_dhist[i];
    __shared__ int wsum[32];
    int lane = tid & 31, w = tid >> 5;
    int v = local;
#pragma unroll
    for (int o = 1; o < 32; o <<= 1) {
        int u = __shfl_up_sync(0xffffffffu, v, o);
        if (lane >= o) v += u;
    }
    if (lane == 31) wsum[w] = v;
    __syncthreads();
    if (w == 0) {
        int s = wsum[lane];
#pragma unroll
        for (int o = 1; o < 32; o <<= 1) {
            int u = __shfl_up_sync(0xffffffffu, s, o);
            if (lane >= o) s += u;
        }
        wsum[lane] = s;
    }
    __syncthreads();
    int run = v - local + (w > 0 ? wsum[w - 1] : 0);
    for (int i = start; i < end; i++) { g_doff[i] = run; run += g_dhist[i]; }
}

__global__ void k_scatter_dst(const int* __restrict__ dst_idx, int E) {
    int e = blockIdx.x * blockDim.x + threadIdx.x;
    if (e < E) {
        int d = dst_idx[e];
        int p = atomicAdd(&g_dcur[d], 1);
        g_dorder[g_doff[d] + p] = e;
    }
}

// ---------------- weight transpose (tiled smem) + bf16 hi/lo split -------
__global__ void k_wconv2(const float* __restrict__ Wq,
                         const float* __restrict__ Wk,
                         const float* __restrict__ Wv) {
    const int which = blockIdx.z;      // 0=Q, 1=K, 2=V
    const int r = blockIdx.y;
    const int KD = (which == 0) ? IN_DIM : CAT_DIM;
    const int ntiles_n = OUT_DIM / 32;
    const int tile = blockIdx.x;
    const int kt = tile / ntiles_n;
    const int nt = tile - kt * ntiles_n;
    if (kt * 32 >= KD) return;

    const float* W = (which == 0 ? Wq : which == 1 ? Wk : Wv)
                   + (size_t)r * KD * OUT_DIM;
    __nv_bfloat16* wh = (which == 0 ? g_wq_hi : which == 1 ? g_wk_hi : g_wv_hi)
                      + (size_t)r * OUT_DIM * KD;
    __nv_bfloat16* wl = (which == 0 ? g_wq_lo : which == 1 ? g_wk_lo : g_wv_lo)
                      + (size_t)r * OUT_DIM * KD;

    __shared__ float smt[32][33];
    const int tx = threadIdx.x, ty = threadIdx.y;  // 32 x 8
#pragma unroll
    for (int dy = 0; dy < 4; dy++) {
        int k = kt * 32 + ty + dy * 8;
        smt[ty + dy * 8][tx] = W[(size_t)k * OUT_DIM + nt * 32 + tx];
    }
    __syncthreads();
#pragma unroll
    for (int dy = 0; dy < 4; dy++) {
        int n = nt * 32 + ty + dy * 8;
        int k = kt * 32 + tx;
        float v = smt[tx][ty + dy * 8];
        __nv_bfloat16 h = __float2bfloat16(v);
        wh[(size_t)n * KD + k] = h;
        wl[(size_t)n * KD + k] = __float2bfloat16(v - __bfloat162float(h));
    }
}

// ---------------- typed projections: fused dia(LN+time-enc) + mma.sync ----
// KV=false: Q = LN_d(dia_d) @ Wq^T (KD=128, rows from dst_idx).
// KV=true:  K,V = LN_s(dia_s) @ Wk^T,Wv^T (KD=160, rows from src_idx+edge_h).
template <int KD, bool KV>
__global__ void __launch_bounds__(512, 1)
k_pm(const float* __restrict__ src_h,
     const float* __restrict__ src_tw,
     const float* __restrict__ src_tb,
     const float* __restrict__ edge_h,
     const float* __restrict__ date,
     const int*   __restrict__ src_idx,
     const int*   __restrict__ dst_idx,
     const float* __restrict__ lng,
     const float* __restrict__ lnb)
{
    const int r = blockIdx.y;
    const int cnt = g_cur[r];
    const int tb = blockIdx.x * TILE_E;
    if (tb >= cnt) return;
    const size_t base = (size_t)r * E_MAX + tb;
    const int ne = min(TILE_E, cnt - tb);

    constexpr int SA  = KD + 8;
    constexpr int SAB = SA * 2;
    constexpr int NK  = KD / 16;
    constexpr int U   = KD / 8;
    constexpr int NR  = KD / 32;   // regs per lane for dia

    extern __shared__ __align__(16) char sm[];
    __nv_bfloat16* aH = (__nv_bfloat16*)sm;
    __nv_bfloat16* aL = aH + 128 * SA;
    __nv_bfloat16* bH = aL + 128 * SA;
    __nv_bfloat16* bL = bH + 128 * SA;
    __shared__ int so[TILE_E];

    const int tid = threadIdx.x, wid = tid >> 5, lane = tid & 31;
    if (tid < TILE_E) so[tid] = (tid < ne) ? g_order[base + tid] : 0;
    __syncthreads();

    // ---- fused dia: one warp per tile row, 8 rows per warp ----
#pragma unroll 1
    for (int w8 = 0; w8 < 8; w8++) {
        const int i = wid * 8 + w8;
        __nv_bfloat16* rowH = aH + i * SA;
        __nv_bfloat16* rowL = aL + i * SA;
        if (i < ne) {
            const int e = so[i];
            const int nd = KV ? src_idx[e] : dst_idx[e];
            const float t = date[e];
            float xs[NR];
#pragma unroll
            for (int k = 0; k < NR; k++) {
                int j = lane + 32 * k;
                float v;
                if (j < TD)
                    v = __sinf(src_tw[(size_t)nd * TD + j] * t +
                               src_tb[(size_t)nd * TD + j]) *
                        src_h[(size_t)nd * IN_DIM + j];
                else if (j < IN_DIM)
                    v = src_h[(size_t)nd * IN_DIM + j];
                else
                    v = edge_h[(size_t)e * E_DIM + (j - IN_DIM)];
                xs[k] = v;
            }
            float sum = 0.f;
#pragma unroll
            for (int k = 0; k < NR; k++) sum += xs[k];
#pragma unroll
            for (int o = 16; o > 0; o >>= 1) sum += __shfl_xor_sync(0xffffffffu, sum, o);
            float mu = sum * (1.0f / KD);
            float vs = 0.f;
#pragma unroll
            for (int k = 0; k < NR; k++) { float dd = xs[k] - mu; vs += dd * dd; }
#pragma unroll
            for (int o = 16; o > 0; o >>= 1) vs += __shfl_xor_sync(0xffffffffu, vs, o);
            float rstd = rsqrtf(vs * (1.0f / KD) + LN_EPS);
#pragma unroll
            for (int k = 0; k < NR; k++) {
                int j = lane + 32 * k;
                float y = (xs[k] - mu) * rstd * lng[j] + lnb[j];
                __nv_bfloat16 h = __float2bfloat16(y);
                rowH[j] = h;
                rowL[j] = __float2bfloat16(y - __bfloat162float(h));
            }
        } else {
#pragma unroll
            for (int k = 0; k < NR; k++) {
                int j = lane + 32 * k;
                rowH[j] = __float2bfloat16(0.f);
                rowL[j] = __float2bfloat16(0.f);
            }
        }
    }
    // ---- stage B (first weight set) ----
    {
        const __nv_bfloat16* wh = (KV ? g_wk_hi : g_wq_hi) + (size_t)r * OUT_DIM * KD;
        const __nv_bfloat16* wl = (KV ? g_wk_lo : g_wq_lo) + (size_t)r * OUT_DIM * KD;
        for (int idx = tid; idx < 128 * U; idx += 512) {
            int n = idx / U, u = idx - n * U;
            *(uint4*)((char*)bH + n * SAB + u * 16) = ((const uint4*)(wh + (size_t)n * KD))[u];
            *(uint4*)((char*)bL + n * SAB + u * 16) = ((const uint4*)(wl + (size_t)n * KD))[u];
        }
    }
    __syncthreads();

    const int stripe = (wid >> 1) * 16;
    const int nhalf  = (wid & 1) * 64;

    const uint32_t aOffH = smem_u32(aH) + (uint32_t)(stripe + (lane & 15)) * SAB
                         + (uint32_t)(lane >> 4) * 16;
    const uint32_t aOffL = aOffH + (uint32_t)(128 * SAB);
    const int brow = ((lane >> 4) & 1) * 8 + (lane & 7);
    const int bko  = ((lane >> 3) & 1) * 16;
    const uint32_t bOffH = smem_u32(bH) + (uint32_t)(nhalf + brow) * SAB + bko;
    const uint32_t bOffL = bOffH + (uint32_t)(128 * SAB);

    float acc[8][4];
#pragma unroll
    for (int j = 0; j < 8; j++)
#pragma unroll
        for (int b = 0; b < 4; b++) acc[j][b] = 0.f;

    auto run_pass = [&](uint32_t aOff, uint32_t bOff) {
#pragma unroll
        for (int ks = 0; ks < NK; ks++) {
            uint32_t a0, a1, a2, a3;
            ldsm4(a0, a1, a2, a3, aOff + ks * 32);
#pragma unroll
            for (int tp = 0; tp < 4; tp++) {
                uint32_t b0, b1, b2, b3;
                ldsm4(b0, b1, b2, b3, bOff + tp * 16 * SAB + ks * 32);
                mma16816(acc[2 * tp],     a0, a1, a2, a3, b0, b1);
                mma16816(acc[2 * tp + 1], a0, a1, a2, a3, b2, b3);
            }
        }
    };
    auto wout = [&](float* outp) {
        int r0 = stripe + (lane >> 2);
        int c  = nhalf + (lane & 3) * 2;
        bool vA = r0 < ne, vB = (r0 + 8) < ne;
        size_t gA = vA ? (size_t)so[r0] * OUT_DIM : 0;
        size_t gB = vB ? (size_t)so[r0 + 8] * OUT_DIM : 0;
#pragma unroll
        for (int j = 0; j < 8; j++) {
            if (vA) *(float2*)&outp[gA + c + j * 8] = make_float2(acc[j][0], acc[j][1]);
            if (vB) *(float2*)&outp[gB + c + j * 8] = make_float2(acc[j][2], acc[j][3]);
        }
    };

    run_pass(aOffH, bOffH);
    run_pass(aOffH, bOffL);
    run_pass(aOffL, bOffH);
    wout(KV ? g_k : g_q);

    if (KV) {
        __syncthreads();
        {
            const __nv_bfloat16* wh = g_wv_hi + (size_t)r * OUT_DIM * KD;
            const __nv_bfloat16* wl = g_wv_lo + (size_t)r * OUT_DIM * KD;
            for (int idx = tid; idx < 128 * U; idx += 512) {
                int n = idx / U, u = idx - n * U;
                *(uint4*)((char*)bH + n * SAB + u * 16) = ((const uint4*)(wh + (size_t)n * KD))[u];
                *(uint4*)((char*)bL + n * SAB + u * 16) = ((const uint4*)(wl + (size_t)n * KD))[u];
            }
        }
        __syncthreads();
#pragma unroll
        for (int j = 0; j < 8; j++)
#pragma unroll
            for (int b = 0; b < 4; b++) acc[j][b] = 0.f;
        run_pass(aOffH, bOffH);
        run_pass(aOffH, bOffL);
        run_pass(aOffL, bOffH);
        wout(g_v);
    }
}

// ---------------- fused attention: logits + online softmax + weighted V ---
// One warp per dst node over the dst-sorted edge list. No atomics.
__global__ void k_attn_fused(int M)
{
    int warp = (blockIdx.x * blockDim.x + threadIdx.x) >> 5;
    int lane = threadIdx.x & 31;
    if (warp >= M) return;
    const int m = warp;
    const int beg = g_doff[m];
    const int cnt = g_dhist[m];
    const int h = lane >> 2;       // head (also = (lane*4)/16 for V phase)
    const int i4 = lane & 3;

    // pass 1: logits + online max/denominator
    float amax = -1e30f, denom = 0.f;
    for (int i = 0; i < cnt; i++) {
        int e = g_dorder[beg + i];
        const float4* qp = (const float4*)&g_q[(size_t)e * OUT_DIM + h * HS];
        const float4* kp = (const float4*)&g_k[(size_t)e * OUT_DIM + h * HS];
        float4 qv = qp[i4], kv = kp[i4];
        float dot = qv.x * kv.x + qv.y * kv.y + qv.z * kv.z + qv.w * kv.w;
        dot += __shfl_xor_sync(0xffffffffu, dot, 1);
        dot += __shfl_xor_sync(0xffffffffu, dot, 2);
        float a = dot * 0.08838834764831845f;   // 1/sqrt(128)
        if (i4 == 0) g_a[(size_t)e * H_HEADS + h] = a;
        float nmax = fmaxf(amax, a);
        denom = denom * __expf(amax - nmax) + __expf(a - nmax);
        amax = nmax;
    }
    float inv = (cnt > 0) ? 1.f / denom : 0.f;

    // pass 2: alpha-weighted V accumulation
    const int c0 = lane * 4;
    float4 acc = make_float4(0.f, 0.f, 0.f, 0.f);
    for (int i = 0; i < cnt; i++) {
        int e = g_dorder[beg + i];
        float a = g_a[(size_t)e * H_HEADS + h];
        float alpha = __expf(a - amax) * inv;
        float4 v = *(const float4*)&g_v[(size_t)e * OUT_DIM + c0];
        acc.x += v.x * alpha;
        acc.y += v.y * alpha;
        acc.z += v.z * alpha;
        acc.w += v.w * alpha;
    }
    *(float4*)&g_hacc[(size_t)m * OUT_DIM + c0] = acc;
}

// ---------------- typed output projection (tiled by ntype) -------------
__global__ void __launch_bounds__(256, 2)
k_out_t(const float* __restrict__ Wa,
        const float* __restrict__ h_bias,
        const float* __restrict__ skip,
        const float* __restrict__ src_h,
        float* __restrict__ out, int M)
{
    const int r = blockIdx.y;
    const int cnt = g_ncur[r];
    const int tbase = blockIdx.x * TILE_M;
    if (tbase >= cnt) return;
    const size_t base = (size_t)r * M_MAX + tbase;
    const int ne = min(TILE_M, cnt - tbase);

    extern __shared__ float smf[];
    float* Ws = smf;
    float* Ds = smf + OUT_DIM * OUT_DIM;
    const int DS = TILE_M + 4;
    __shared__ int no[TILE_M];

    const int tid = threadIdx.x;
    if (tid < TILE_M) no[tid] = (tid < ne) ? g_norder[base + tid] : 0;
    __syncthreads();

    {
        const float* W = Wa + (size_t)r * OUT_DIM * OUT_DIM;
        for (int idx = tid; idx < OUT_DIM * (OUT_DIM / 4); idx += 256)
            ((float4*)Ws)[idx] = ((const float4*)W)[idx];
    }
    for (int idx = tid; idx < TILE_M * OUT_DIM; idx += 256) {
        int m = idx >> 7;
        int i = idx & 127;
        Ds[i * DS + m] = (m < ne) ?
            g_hacc[(size_t)no[m] * OUT_DIM + i] + h_bias[(size_t)r * OUT_DIM + i] : 0.f;
    }
    __syncthreads();

    const int c0 = (tid & 31) * 4;
    const int m0 = (tid >> 5) * 8;
    ull acc[4][4];
#pragma unroll
    for (int p = 0; p < 4; p++)
#pragma unroll
        for (int b = 0; b < 4; b++) acc[p][b] = 0ull;

#pragma unroll 8
    for (int i = 0; i < OUT_DIM; i++) {
        float4 w = *(const float4*)&Ws[i * OUT_DIM + c0];
        ull wd0 = dup2(w.x), wd1 = dup2(w.y), wd2 = dup2(w.z), wd3 = dup2(w.w);
        ulonglong2 p0 = *(const ulonglong2*)&Ds[i * DS + m0];
        ulonglong2 p1 = *(const ulonglong2*)&Ds[i * DS + m0 + 4];
        ull de[4] = {p0.x, p0.y, p1.x, p1.y};
#pragma unroll
        for (int p = 0; p < 4; p++) {
            acc[p][0] = fma2(de[p], wd0, acc[p][0]);
            acc[p][1] = fma2(de[p], wd1, acc[p][1]);
            acc[p][2] = fma2(de[p], wd2, acc[p][2]);
            acc[p][3] = fma2(de[p], wd3, acc[p][3]);
        }
    }

    float gate = 1.f / (1.f + __expf(-skip[r]));
    float og = 1.f - gate;
#pragma unroll
    for (int p = 0; p < 4; p++) {
        float2 v0 = unpk(acc[p][0]);
        float2 v1 = unpk(acc[p][1]);
        float2 v2 = unpk(acc[p][2]);
        float2 v3 = unpk(acc[p][3]);
        int mA = m0 + 2 * p, mB = mA + 1;
        if (mA < ne) {
            size_t gm = (size_t)no[mA] * OUT_DIM + c0;
            float4 s = *(const float4*)&src_h[gm];
            *(float4*)&out[gm] = make_float4(v0.x * gate + s.x * og,
                                             v1.x * gate + s.y * og,
                                             v2.x * gate + s.z * og,
                                             v3.x * gate + s.w * og);
        }
        if (mB < ne) {
            size_t gm = (size_t)no[mB] * OUT_DIM + c0;
            float4 s = *(const float4*)&src_h[gm];
            *(float4*)&out[gm] = make_float4(v0.y * gate + s.x * og,
                                             v1.y * gate + s.y * og,
                                             v2.y * gate + s.z * og,
                                             v3.y * gate + s.w * og);
        }
    }
}

// ---------------- launch ----------------
extern "C" void kernel_launch(void* const* d_in, const int* in_sizes, int n_in,
                              void* d_out, int out_size)
{
    const float* src_h  = (const float*)d_in[0];
    const float* src_tw = (const float*)d_in[1];
    const float* src_tb = (const float*)d_in[2];
    const float* edge_h = (const float*)d_in[3];
    const float* date   = (const float*)d_in[4];
    const int*   src_idx = (const int*)d_in[5];
    const int*   dst_idx = (const int*)d_in[6];
    const int*   etype   = (const int*)d_in[7];
    const int*   ntype   = (const int*)d_in[8];
    const float* Wq = (const float*)d_in[9];
    const float* Wk = (const float*)d_in[10];
    const float* Wv = (const float*)d_in[11];
    const float* Wa = (const float*)d_in[12];
    const float* h_bias = (const float*)d_in[13];
    const float* skip   = (const float*)d_in[14];
    const float* sg = (const float*)d_in[15];
    const float* sb = (const float*)d_in[16];
    const float* dg = (const float*)d_in[17];
    const float* db = (const float*)d_in[18];
    float* out = (float*)d_out;

    const int E = in_sizes[4];
    const int M = in_sizes[8];

    const int SMQ  = 4 * 128 * (IN_DIM + 8) * 2;    // 139264
    const int SMKV = 4 * 128 * (CAT_DIM + 8) * 2;   // 172032
    const int SMO  = (OUT_DIM * OUT_DIM + OUT_DIM * (TILE_M + 4)) * 4;
    cudaFuncSetAttribute(k_pm<IN_DIM, false>, cudaFuncAttributeMaxDynamicSharedMemorySize, SMQ);
    cudaFuncSetAttribute(k_pm<CAT_DIM, true>, cudaFuncAttributeMaxDynamicSharedMemorySize, SMKV);
    cudaFuncSetAttribute(k_out_t, cudaFuncAttributeMaxDynamicSharedMemorySize, SMO);

    int mx = (E > M) ? E : M;
    k_reset<<<(M + 255) / 256, 256>>>(M);
    k_scatter_all<<<(mx + 255) / 256, 256>>>(etype, ntype, dst_idx, E, M);
    k_scan_dst<<<1, 1024>>>(M);
    k_scatter_dst<<<(E + 255) / 256, 256>>>(dst_idx, E);
    {
        dim3 gw((CAT_DIM / 32) * (OUT_DIM / 32), R_TYPES, 3);
        k_wconv2<<<gw, dim3(32, 8)>>>(Wq, Wk, Wv);
    }
    dim3 gq((E + TILE_E - 1) / TILE_E, R_TYPES);
    k_pm<IN_DIM,  false><<<gq, 512, SMQ >>>(src_h, src_tw, src_tb, edge_h, date,
                                            src_idx, dst_idx, dg, db);
    k_pm<CAT_DIM, true ><<<gq, 512, SMKV>>>(src_h, src_tw, src_tb, edge_h, date,
                                            src_idx, dst_idx, sg, sb);
    k_attn_fused<<<(M * 32 + 255) / 256, 256>>>(M);
    dim3 go((M + TILE_M - 1) / TILE_M, T_TYPES);
    k_out_t<<<go, 256, SMO>>>(Wa, h_bias, skip, src_h, out, M);
}

// round 12
// speedup vs baseline: 1.2702x; 1.2702x over previous
#include <cuda_runtime.h>
#include <cuda_bf16.h>
#include <math.h>
#include <stdint.h>

// ---------------- problem constants ----------------
#define IN_DIM   128
#define E_DIM    32
#define CAT_DIM  160
#define OUT_DIM  128
#define TD       32
#define H_HEADS  8
#define HS       16
#define R_TYPES  8
#define T_TYPES  4
#define LN_EPS   1e-5f
#define E_MAX    100000
#define M_MAX    10000
#define TILE_E   128
#define TILE_M   64

typedef unsigned long long ull;

// ---------------- device scratch ----------------
__device__ __nv_bfloat16 g_wq_hi[(size_t)R_TYPES * OUT_DIM * IN_DIM];
__device__ __nv_bfloat16 g_wq_lo[(size_t)R_TYPES * OUT_DIM * IN_DIM];
__device__ __nv_bfloat16 g_wk_hi[(size_t)R_TYPES * OUT_DIM * CAT_DIM];
__device__ __nv_bfloat16 g_wk_lo[(size_t)R_TYPES * OUT_DIM * CAT_DIM];
__device__ __nv_bfloat16 g_wv_hi[(size_t)R_TYPES * OUT_DIM * CAT_DIM];
__device__ __nv_bfloat16 g_wv_lo[(size_t)R_TYPES * OUT_DIM * CAT_DIM];

__device__ float    g_v[(size_t)E_MAX * OUT_DIM];
__device__ float    g_a[(size_t)E_MAX * H_HEADS];
__device__ float    g_hacc[(size_t)M_MAX * OUT_DIM];

__device__ int      g_cur[R_TYPES];
__device__ int      g_order[(size_t)R_TYPES * E_MAX];
__device__ int      g_ncur[T_TYPES];
__device__ int      g_norder[(size_t)T_TYPES * M_MAX];
__device__ int      g_dhist[M_MAX], g_doff[M_MAX], g_dcur[M_MAX];
__device__ int      g_dorder[E_MAX];

// ---------------- f32x2 packed-FMA helpers (k_out) ----------------
__device__ __forceinline__ ull fma2(ull a, ull b, ull c) {
    ull d;
    asm("fma.rn.f32x2 %0, %1, %2, %3;" : "=l"(d) : "l"(a), "l"(b), "l"(c));
    return d;
}
__device__ __forceinline__ ull dup2(float x) {
    ull d; asm("mov.b64 %0, {%1, %1};" : "=l"(d) : "f"(x)); return d;
}
__device__ __forceinline__ float2 unpk(ull v) {
    float2 f; asm("mov.b64 {%0, %1}, %2;" : "=f"(f.x), "=f"(f.y) : "l"(v)); return f;
}

// ---------------- mma.sync helpers ----------------
__device__ __forceinline__ uint32_t smem_u32(const void* p) {
    uint32_t a;
    asm("{ .reg .u64 t; cvta.to.shared.u64 t, %1; cvt.u32.u64 %0, t; }"
        : "=r"(a) : "l"(p));
    return a;
}
__device__ __forceinline__ void ldsm4(uint32_t& r0, uint32_t& r1, uint32_t& r2,
                                      uint32_t& r3, uint32_t addr) {
    asm volatile("ldmatrix.sync.aligned.m8n8.x4.shared.b16 {%0,%1,%2,%3}, [%4];"
                 : "=r"(r0), "=r"(r1), "=r"(r2), "=r"(r3) : "r"(addr));
}
__device__ __forceinline__ void mma16816(float* d, uint32_t a0, uint32_t a1,
                                         uint32_t a2, uint32_t a3,
                                         uint32_t b0, uint32_t b1) {
    asm volatile(
        "mma.sync.aligned.m16n8k16.row.col.f32.bf16.bf16.f32 "
        "{%0,%1,%2,%3}, {%4,%5,%6,%7}, {%8,%9}, {%0,%1,%2,%3};"
        : "+f"(d[0]), "+f"(d[1]), "+f"(d[2]), "+f"(d[3])
        : "r"(a0), "r"(a1), "r"(a2), "r"(a3), "r"(b0), "r"(b1));
}

// ---------------- reset ----------------
__global__ void k_reset(int M) {
    int t = blockIdx.x * blockDim.x + threadIdx.x;
    if (t < M)       { g_dhist[t] = 0; g_dcur[t] = 0; }
    if (t < R_TYPES) g_cur[t] = 0;
    if (t < T_TYPES) g_ncur[t] = 0;
}

// ---------------- scatter: etype buckets, ntype buckets, dst histogram ----
__global__ void k_scatter_all(const int* __restrict__ etype,
                              const int* __restrict__ ntype,
                              const int* __restrict__ dst_idx,
                              int E, int M) {
    int t = blockIdx.x * blockDim.x + threadIdx.x;
    int lane = threadIdx.x & 31;
    unsigned actE = __ballot_sync(0xffffffffu, t < E);
    if (t < E) {
        int r = etype[t];
        unsigned m = __match_any_sync(actE, r);
        int leader = __ffs(m) - 1;
        int rank = __popc(m & ((1u << lane) - 1));
        int base = 0;
        if (lane == leader) base = atomicAdd(&g_cur[r], __popc(m));
        base = __shfl_sync(actE, base, leader);
        g_order[(size_t)r * E_MAX + base + rank] = t;
        atomicAdd(&g_dhist[dst_idx[t]], 1);
    }
    unsigned actM = __ballot_sync(0xffffffffu, t < M);
    if (t < M) {
        int r = ntype[t];
        unsigned m = __match_any_sync(actM, r);
        int leader = __ffs(m) - 1;
        int rank = __popc(m & ((1u << lane) - 1));
        int base = 0;
        if (lane == leader) base = atomicAdd(&g_ncur[r], __popc(m));
        base = __shfl_sync(actM, base, leader);
        g_norder[(size_t)r * M_MAX + base + rank] = t;
    }
}

// ---------------- single-block exclusive scan of g_dhist -> g_doff -------
__global__ void __launch_bounds__(1024, 1) k_scan_dst(int M) {
    const int tid = threadIdx.x;
    const int per = (M + 1023) / 1024;
    const int start = tid * per;
    const int end = min(start + per, M);
    int local = 0;
    for (int i = start; i < end; i++) local += g_dhist[i];
    __shared__ int wsum[32];
    int lane = tid & 31, w = tid >> 5;
    int v = local;
#pragma unroll
    for (int o = 1; o < 32; o <<= 1) {
        int u = __shfl_up_sync(0xffffffffu, v, o);
        if (lane >= o) v += u;
    }
    if (lane == 31) wsum[w] = v;
    __syncthreads();
    if (w == 0) {
        int s = wsum[lane];
#pragma unroll
        for (int o = 1; o < 32; o <<= 1) {
            int u = __shfl_up_sync(0xffffffffu, s, o);
            if (lane >= o) s += u;
        }
        wsum[lane] = s;
    }
    __syncthreads();
    int run = v - local + (w > 0 ? wsum[w - 1] : 0);
    for (int i = start; i < end; i++) { g_doff[i] = run; run += g_dhist[i]; }
}

__global__ void k_scatter_dst(const int* __restrict__ dst_idx, int E) {
    int e = blockIdx.x * blockDim.x + threadIdx.x;
    if (e < E) {
        int d = dst_idx[e];
        int p = atomicAdd(&g_dcur[d], 1);
        g_dorder[g_doff[d] + p] = e;
    }
}

// ---------------- weight transpose (tiled smem) + bf16 hi/lo split -------
__global__ void k_wconv2(const float* __restrict__ Wq,
                         const float* __restrict__ Wk,
                         const float* __restrict__ Wv) {
    const int which = blockIdx.z;      // 0=Q, 1=K, 2=V
    const int r = blockIdx.y;
    const int KD = (which == 0) ? IN_DIM : CAT_DIM;
    const int ntiles_n = OUT_DIM / 32;
    const int tile = blockIdx.x;
    const int kt = tile / ntiles_n;
    const int nt = tile - kt * ntiles_n;
    if (kt * 32 >= KD) return;

    const float* W = (which == 0 ? Wq : which == 1 ? Wk : Wv)
                   + (size_t)r * KD * OUT_DIM;
    __nv_bfloat16* wh = (which == 0 ? g_wq_hi : which == 1 ? g_wk_hi : g_wv_hi)
                      + (size_t)r * OUT_DIM * KD;
    __nv_bfloat16* wl = (which == 0 ? g_wq_lo : which == 1 ? g_wk_lo : g_wv_lo)
                      + (size_t)r * OUT_DIM * KD;

    __shared__ float smt[32][33];
    const int tx = threadIdx.x, ty = threadIdx.y;  // 32 x 8
#pragma unroll
    for (int dy = 0; dy < 4; dy++) {
        int k = kt * 32 + ty + dy * 8;
        smt[ty + dy * 8][tx] = W[(size_t)k * OUT_DIM + nt * 32 + tx];
    }
    __syncthreads();
#pragma unroll
    for (int dy = 0; dy < 4; dy++) {
        int n = nt * 32 + ty + dy * 8;
        int k = kt * 32 + tx;
        float v = smt[tx][ty + dy * 8];
        __nv_bfloat16 h = __float2bfloat16(v);
        wh[(size_t)n * KD + k] = h;
        wl[(size_t)n * KD + k] = __float2bfloat16(v - __bfloat162float(h));
    }
}

// ---------------- fully fused QKV + logits kernel ----------------
// Per (etype, tile-of-128-edges) block:
//   phase A: LN(src)+time-enc -> A_s smem planes; B=Wk -> K fragments (regs)
//   phase B: B=Wv -> V fragments -> g_v
//   phase C: LN(dst) -> A_d smem planes; B=Wq -> Q fragments
//   logits:  a[e][h] = (Q.K)/sqrt(128) from register fragments -> g_a
#define SA  (CAT_DIM + 8)     // unified row stride (bf16 elems) = 168
#define SAB (SA * 2)          // 336 bytes

__global__ void __launch_bounds__(512, 1)
k_qkv(const float* __restrict__ src_h,
      const float* __restrict__ src_tw,
      const float* __restrict__ src_tb,
      const float* __restrict__ edge_h,
      const float* __restrict__ date,
      const int*   __restrict__ src_idx,
      const int*   __restrict__ dst_idx,
      const float* __restrict__ sg, const float* __restrict__ sb,
      const float* __restrict__ dg, const float* __restrict__ db)
{
    const int r = blockIdx.y;
    const int cnt = g_cur[r];
    const int tb = blockIdx.x * TILE_E;
    if (tb >= cnt) return;
    const size_t base = (size_t)r * E_MAX + tb;
    const int ne = min(TILE_E, cnt - tb);

    extern __shared__ __align__(16) char sm[];
    __nv_bfloat16* aH = (__nv_bfloat16*)sm;
    __nv_bfloat16* aL = aH + 128 * SA;
    __nv_bfloat16* bH = aL + 128 * SA;
    __nv_bfloat16* bL = bH + 128 * SA;
    __shared__ int so[TILE_E];

    const int tid = threadIdx.x, wid = tid >> 5, lane = tid & 31;
    if (tid < TILE_E) so[tid] = (tid < ne) ? g_order[base + tid] : 0;
    __syncthreads();

    // ---------- MLP-friendly fused LN staging: 8 rows per warp ----------
    // SRC=true: 160 dims (sin+h | h | edge), gamma/beta = sg/sb
    // SRC=false: 128 dims, gamma/beta = dg/db
    auto stage_ln = [&](bool SRC) {
        const int NR = SRC ? 5 : 4;
        const float inv_kd = SRC ? (1.0f / CAT_DIM) : (1.0f / IN_DIM);
        const float* lng = SRC ? sg : dg;
        const float* lnb = SRC ? sb : db;
        int   eA[8]; int ndA[8]; float tA[8];
#pragma unroll
        for (int w8 = 0; w8 < 8; w8++) {
            int i = wid * 8 + w8;
            int e = so[i < ne ? i : 0];
            eA[w8] = e;
            ndA[w8] = SRC ? src_idx[e] : dst_idx[e];
            tA[w8] = date[e];
        }
        float xs[8][5];
#pragma unroll
        for (int w8 = 0; w8 < 8; w8++) {
            int nd = ndA[w8];
            xs[w8][0] = __sinf(src_tw[(size_t)nd * TD + lane] * tA[w8] +
                               src_tb[(size_t)nd * TD + lane]) *
                        src_h[(size_t)nd * IN_DIM + lane];
#pragma unroll
            for (int k = 1; k < 4; k++)
                xs[w8][k] = src_h[(size_t)nd * IN_DIM + lane + 32 * k];
            if (SRC) xs[w8][4] = edge_h[(size_t)eA[w8] * E_DIM + lane];
        }
        float mu[8], rstd[8];
#pragma unroll
        for (int w8 = 0; w8 < 8; w8++) {
            float s = 0.f;
            for (int k = 0; k < NR; k++) s += xs[w8][k];
#pragma unroll
            for (int o = 16; o > 0; o >>= 1) s += __shfl_xor_sync(0xffffffffu, s, o);
            mu[w8] = s * inv_kd;
        }
#pragma unroll
        for (int w8 = 0; w8 < 8; w8++) {
            float s = 0.f;
            for (int k = 0; k < NR; k++) { float d = xs[w8][k] - mu[w8]; s += d * d; }
#pragma unroll
            for (int o = 16; o > 0; o >>= 1) s += __shfl_xor_sync(0xffffffffu, s, o);
            rstd[w8] = rsqrtf(s * inv_kd + LN_EPS);
        }
#pragma unroll
        for (int w8 = 0; w8 < 8; w8++) {
            int i = wid * 8 + w8;
            __nv_bfloat16* rowH = aH + i * SA;
            __nv_bfloat16* rowL = aL + i * SA;
            bool valid = i < ne;
            for (int k = 0; k < NR; k++) {
                int j = lane + 32 * k;
                float y = valid ? (xs[w8][k] - mu[w8]) * rstd[w8] * lng[j] + lnb[j] : 0.f;
                __nv_bfloat16 h = __float2bfloat16(y);
                rowH[j] = h;
                rowL[j] = __float2bfloat16(y - __bfloat162float(h));
            }
        }
    };

    auto stage_B = [&](const __nv_bfloat16* wh, const __nv_bfloat16* wl, int U) {
        for (int idx = tid; idx < 128 * U; idx += 512) {
            int n = idx / U, u = idx - n * U;
            *(uint4*)((char*)bH + n * SAB + u * 16) = ((const uint4*)(wh + (size_t)n * (U * 8)))[u];
            *(uint4*)((char*)bL + n * SAB + u * 16) = ((const uint4*)(wl + (size_t)n * (U * 8)))[u];
        }
    };

    const int stripe = (wid >> 1) * 16;
    const int nhalf  = (wid & 1) * 64;

    const uint32_t aOffH = smem_u32(aH) + (uint32_t)(stripe + (lane & 15)) * SAB
                         + (uint32_t)(lane >> 4) * 16;
    const uint32_t aOffL = aOffH + (uint32_t)(128 * SAB);
    const int brow = ((lane >> 4) & 1) * 8 + (lane & 7);
    const int bko  = ((lane >> 3) & 1) * 16;
    const uint32_t bOffH = smem_u32(bH) + (uint32_t)(nhalf + brow) * SAB + bko;
    const uint32_t bOffL = bOffH + (uint32_t)(128 * SAB);

    float acc[8][4], kacc[8][4];

    auto zero_acc = [&]() {
#pragma unroll
        for (int j = 0; j < 8; j++)
#pragma unroll
            for (int b = 0; b < 4; b++) acc[j][b] = 0.f;
    };
    auto run_pass = [&](uint32_t aOff, uint32_t bOff, int nk) {
#pragma unroll
        for (int ks = 0; ks < 10; ks++) {
            if (ks >= nk) break;
            uint32_t a0, a1, a2, a3;
            ldsm4(a0, a1, a2, a3, aOff + ks * 32);
#pragma unroll
            for (int tp = 0; tp < 4; tp++) {
                uint32_t b0, b1, b2, b3;
                ldsm4(b0, b1, b2, b3, bOff + tp * 16 * SAB + ks * 32);
                mma16816(acc[2 * tp],     a0, a1, a2, a3, b0, b1);
                mma16816(acc[2 * tp + 1], a0, a1, a2, a3, b2, b3);
            }
        }
    };
    auto run3 = [&](int nk) {
        run_pass(aOffH, bOffH, nk);
        run_pass(aOffH, bOffL, nk);
        run_pass(aOffL, bOffH, nk);
    };

    // ---- phase A: A_s + Wk -> K fragments ----
    stage_ln(true);
    stage_B(g_wk_hi + (size_t)r * OUT_DIM * CAT_DIM,
            g_wk_lo + (size_t)r * OUT_DIM * CAT_DIM, CAT_DIM / 8);
    __syncthreads();
    zero_acc();
    run3(CAT_DIM / 16);
#pragma unroll
    for (int j = 0; j < 8; j++)
#pragma unroll
        for (int b = 0; b < 4; b++) kacc[j][b] = acc[j][b];

    // ---- phase B: Wv -> V -> g_v ----
    __syncthreads();
    stage_B(g_wv_hi + (size_t)r * OUT_DIM * CAT_DIM,
            g_wv_lo + (size_t)r * OUT_DIM * CAT_DIM, CAT_DIM / 8);
    __syncthreads();
    zero_acc();
    run3(CAT_DIM / 16);
    {
        int r0 = stripe + (lane >> 2);
        int c  = nhalf + (lane & 3) * 2;
        bool vA = r0 < ne, vB = (r0 + 8) < ne;
        size_t gA = vA ? (size_t)so[r0] * OUT_DIM : 0;
        size_t gB = vB ? (size_t)so[r0 + 8] * OUT_DIM : 0;
#pragma unroll
        for (int j = 0; j < 8; j++) {
            if (vA) *(float2*)&g_v[gA + c + j * 8] = make_float2(acc[j][0], acc[j][1]);
            if (vB) *(float2*)&g_v[gB + c + j * 8] = make_float2(acc[j][2], acc[j][3]);
        }
    }

    // ---- phase C: A_d + Wq -> Q fragments ----
    __syncthreads();
    stage_ln(false);
    stage_B(g_wq_hi + (size_t)r * OUT_DIM * IN_DIM,
            g_wq_lo + (size_t)r * OUT_DIM * IN_DIM, IN_DIM / 8);
    __syncthreads();
    zero_acc();
    run3(IN_DIM / 16);

    // ---- logits from fragments: a[e][h] = (q.k)/sqrt(128) ----
    {
        int r0 = stripe + (lane >> 2);
        bool vA = r0 < ne, vB = (r0 + 8) < ne;
#pragma unroll
        for (int hl = 0; hl < 4; hl++) {
            float sA = 0.f, sB = 0.f;
#pragma unroll
            for (int jj = 0; jj < 2; jj++) {
                int j = 2 * hl + jj;
                sA += acc[j][0] * kacc[j][0] + acc[j][1] * kacc[j][1];
                sB += acc[j][2] * kacc[j][2] + acc[j][3] * kacc[j][3];
            }
            sA += __shfl_xor_sync(0xffffffffu, sA, 1);
            sA += __shfl_xor_sync(0xffffffffu, sA, 2);
            sB += __shfl_xor_sync(0xffffffffu, sB, 1);
            sB += __shfl_xor_sync(0xffffffffu, sB, 2);
            if ((lane & 3) == 0) {
                int h = (wid & 1) * 4 + hl;
                if (vA) g_a[(size_t)so[r0] * H_HEADS + h] =
                            sA * 0.08838834764831845f;
                if (vB) g_a[(size_t)so[r0 + 8] * H_HEADS + h] =
                            sB * 0.08838834764831845f;
            }
        }
    }
}

// ---------------- fused softmax + weighted V (warp per node) ----------
__global__ void k_attn2(int M)
{
    int warp = (blockIdx.x * blockDim.x + threadIdx.x) >> 5;
    int lane = threadIdx.x & 31;
    if (warp >= M) return;
    const int m = warp;
    const int beg = g_doff[m];
    const int cnt = g_dhist[m];
    const int h = lane >> 2;

    float amax = -1e30f, denom = 0.f;
    for (int i = 0; i < cnt; i++) {
        int e = g_dorder[beg + i];
        float a = g_a[(size_t)e * H_HEADS + h];
        float nmax = fmaxf(amax, a);
        denom = denom * __expf(amax - nmax) + __expf(a - nmax);
        amax = nmax;
    }
    float inv = (cnt > 0) ? 1.f / denom : 0.f;

    const int c0 = lane * 4;
    float4 acc = make_float4(0.f, 0.f, 0.f, 0.f);
    for (int i = 0; i < cnt; i++) {
        int e = g_dorder[beg + i];
        float a = g_a[(size_t)e * H_HEADS + h];
        float alpha = __expf(a - amax) * inv;
        float4 v = *(const float4*)&g_v[(size_t)e * OUT_DIM + c0];
        acc.x += v.x * alpha;
        acc.y += v.y * alpha;
        acc.z += v.z * alpha;
        acc.w += v.w * alpha;
    }
    *(float4*)&g_hacc[(size_t)m * OUT_DIM + c0] = acc;
}

// ---------------- typed output projection (tiled by ntype) -------------
__global__ void __launch_bounds__(256, 2)
k_out_t(const float* __restrict__ Wa,
        const float* __restrict__ h_bias,
        const float* __restrict__ skip,
        const float* __restrict__ src_h,
        float* __restrict__ out, int M)
{
    const int r = blockIdx.y;
    const int cnt = g_ncur[r];
    const int tbase = blockIdx.x * TILE_M;
    if (tbase >= cnt) return;
    const size_t base = (size_t)r * M_MAX + tbase;
    const int ne = min(TILE_M, cnt - tbase);

    extern __shared__ float smf[];
    float* Ws = smf;
    float* Ds = smf + OUT_DIM * OUT_DIM;
    const int DS = TILE_M + 4;
    __shared__ int no[TILE_M];

    const int tid = threadIdx.x;
    if (tid < TILE_M) no[tid] = (tid < ne) ? g_norder[base + tid] : 0;
    __syncthreads();

    {
        const float* W = Wa + (size_t)r * OUT_DIM * OUT_DIM;
        for (int idx = tid; idx < OUT_DIM * (OUT_DIM / 4); idx += 256)
            ((float4*)Ws)[idx] = ((const float4*)W)[idx];
    }
    for (int idx = tid; idx < TILE_M * OUT_DIM; idx += 256) {
        int m = idx >> 7;
        int i = idx & 127;
        Ds[i * DS + m] = (m < ne) ?
            g_hacc[(size_t)no[m] * OUT_DIM + i] + h_bias[(size_t)r * OUT_DIM + i] : 0.f;
    }
    __syncthreads();

    const int c0 = (tid & 31) * 4;
    const int m0 = (tid >> 5) * 8;
    ull acc[4][4];
#pragma unroll
    for (int p = 0; p < 4; p++)
#pragma unroll
        for (int b = 0; b < 4; b++) acc[p][b] = 0ull;

#pragma unroll 8
    for (int i = 0; i < OUT_DIM; i++) {
        float4 w = *(const float4*)&Ws[i * OUT_DIM + c0];
        ull wd0 = dup2(w.x), wd1 = dup2(w.y), wd2 = dup2(w.z), wd3 = dup2(w.w);
        ulonglong2 p0 = *(const ulonglong2*)&Ds[i * DS + m0];
        ulonglong2 p1 = *(const ulonglong2*)&Ds[i * DS + m0 + 4];
        ull de[4] = {p0.x, p0.y, p1.x, p1.y};
#pragma unroll
        for (int p = 0; p < 4; p++) {
            acc[p][0] = fma2(de[p], wd0, acc[p][0]);
            acc[p][1] = fma2(de[p], wd1, acc[p][1]);
            acc[p][2] = fma2(de[p], wd2, acc[p][2]);
            acc[p][3] = fma2(de[p], wd3, acc[p][3]);
        }
    }

    float gate = 1.f / (1.f + __expf(-skip[r]));
    float og = 1.f - gate;
#pragma unroll
    for (int p = 0; p < 4; p++) {
        float2 v0 = unpk(acc[p][0]);
        float2 v1 = unpk(acc[p][1]);
        float2 v2 = unpk(acc[p][2]);
        float2 v3 = unpk(acc[p][3]);
        int mA = m0 + 2 * p, mB = mA + 1;
        if (mA < ne) {
            size_t gm = (size_t)no[mA] * OUT_DIM + c0;
            float4 s = *(const float4*)&src_h[gm];
            *(float4*)&out[gm] = make_float4(v0.x * gate + s.x * og,
                                             v1.x * gate + s.y * og,
                                             v2.x * gate + s.z * og,
                                             v3.x * gate + s.w * og);
        }
        if (mB < ne) {
            size_t gm = (size_t)no[mB] * OUT_DIM + c0;
            float4 s = *(const float4*)&src_h[gm];
            *(float4*)&out[gm] = make_float4(v0.y * gate + s.x * og,
                                             v1.y * gate + s.y * og,
                                             v2.y * gate + s.z * og,
                                             v3.y * gate + s.w * og);
        }
    }
}

// ---------------- launch ----------------
extern "C" void kernel_launch(void* const* d_in, const int* in_sizes, int n_in,
                              void* d_out, int out_size)
{
    const float* src_h  = (const float*)d_in[0];
    const float* src_tw = (const float*)d_in[1];
    const float* src_tb = (const float*)d_in[2];
    const float* edge_h = (const float*)d_in[3];
    const float* date   = (const float*)d_in[4];
    const int*   src_idx = (const int*)d_in[5];
    const int*   dst_idx = (const int*)d_in[6];
    const int*   etype   = (const int*)d_in[7];
    const int*   ntype   = (const int*)d_in[8];
    const float* Wq = (const float*)d_in[9];
    const float* Wk = (const float*)d_in[10];
    const float* Wv = (const float*)d_in[11];
    const float* Wa = (const float*)d_in[12];
    const float* h_bias = (const float*)d_in[13];
    const float* skip   = (const float*)d_in[14];
    const float* sg = (const float*)d_in[15];
    const float* sb = (const float*)d_in[16];
    const float* dg = (const float*)d_in[17];
    const float* db = (const float*)d_in[18];
    float* out = (float*)d_out;

    const int E = in_sizes[4];
    const int M = in_sizes[8];

    const int SMF = 4 * 128 * SA * 2;  // 172032
    const int SMO = (OUT_DIM * OUT_DIM + OUT_DIM * (TILE_M + 4)) * 4;
    cudaFuncSetAttribute(k_qkv, cudaFuncAttributeMaxDynamicSharedMemorySize, SMF);
    cudaFuncSetAttribute(k_out_t, cudaFuncAttributeMaxDynamicSharedMemorySize, SMO);

    int mx = (E > M) ? E : M;
    k_reset<<<(M + 255) / 256, 256>>>(M);
    k_scatter_all<<<(mx + 255) / 256, 256>>>(etype, ntype, dst_idx, E, M);
    k_scan_dst<<<1, 1024>>>(M);
    k_scatter_dst<<<(E + 255) / 256, 256>>>(dst_idx, E);
    {
        dim3 gw((CAT_DIM / 32) * (OUT_DIM / 32), R_TYPES, 3);
        k_wconv2<<<gw, dim3(32, 8)>>>(Wq, Wk, Wv);
    }
    dim3 gq((E + TILE_E - 1) / TILE_E, R_TYPES);
    k_qkv<<<gq, 512, SMF>>>(src_h, src_tw, src_tb, edge_h, date,
                            src_idx, dst_idx, sg, sb, dg, db);
    k_attn2<<<(M * 32 + 255) / 256, 256>>>(M);
    dim3 go((M + TILE_M - 1) / TILE_M, T_TYPES);
    k_out_t<<<go, 256, SMO>>>(Wa, h_bias, skip, src_h, out, M);
}

// round 13
// speedup vs baseline: 1.6619x; 1.3083x over previous
#include <cuda_runtime.h>
#include <cuda_bf16.h>
#include <math.h>
#include <stdint.h>

// ---------------- problem constants ----------------
#define IN_DIM   128
#define E_DIM    32
#define CAT_DIM  160
#define OUT_DIM  128
#define TD       32
#define H_HEADS  8
#define HS       16
#define R_TYPES  8
#define T_TYPES  4
#define LN_EPS   1e-5f
#define E_MAX    100000
#define M_MAX    10000
#define TILE_E   128
#define TILE_M   64

typedef unsigned long long ull;

// ---------------- device scratch ----------------
__device__ __nv_bfloat16 g_wq_hi[(size_t)R_TYPES * OUT_DIM * IN_DIM];
__device__ __nv_bfloat16 g_wq_lo[(size_t)R_TYPES * OUT_DIM * IN_DIM];
__device__ __nv_bfloat16 g_wk_hi[(size_t)R_TYPES * OUT_DIM * CAT_DIM];
__device__ __nv_bfloat16 g_wk_lo[(size_t)R_TYPES * OUT_DIM * CAT_DIM];
__device__ __nv_bfloat16 g_wv_hi[(size_t)R_TYPES * OUT_DIM * CAT_DIM];
__device__ __nv_bfloat16 g_wv_lo[(size_t)R_TYPES * OUT_DIM * CAT_DIM];

__device__ float    g_v[(size_t)E_MAX * OUT_DIM];
__device__ float    g_a[(size_t)E_MAX * H_HEADS];
__device__ float    g_hacc[(size_t)M_MAX * OUT_DIM];

__device__ int      g_cur[R_TYPES];
__device__ int      g_order[(size_t)R_TYPES * E_MAX];
__device__ int      g_ncur[T_TYPES];
__device__ int      g_norder[(size_t)T_TYPES * M_MAX];
__device__ int      g_dhist[M_MAX], g_doff[M_MAX], g_dcur[M_MAX];
__device__ int      g_dorder[E_MAX];

// ---------------- f32x2 packed-FMA helpers (k_out) ----------------
__device__ __forceinline__ ull fma2(ull a, ull b, ull c) {
    ull d;
    asm("fma.rn.f32x2 %0, %1, %2, %3;" : "=l"(d) : "l"(a), "l"(b), "l"(c));
    return d;
}
__device__ __forceinline__ ull dup2(float x) {
    ull d; asm("mov.b64 %0, {%1, %1};" : "=l"(d) : "f"(x)); return d;
}
__device__ __forceinline__ float2 unpk(ull v) {
    float2 f; asm("mov.b64 {%0, %1}, %2;" : "=f"(f.x), "=f"(f.y) : "l"(v)); return f;
}

// ---------------- mma.sync helpers ----------------
__device__ __forceinline__ uint32_t smem_u32(const void* p) {
    uint32_t a;
    asm("{ .reg .u64 t; cvta.to.shared.u64 t, %1; cvt.u32.u64 %0, t; }"
        : "=r"(a) : "l"(p));
    return a;
}
__device__ __forceinline__ void ldsm4(uint32_t& r0, uint32_t& r1, uint32_t& r2,
                                      uint32_t& r3, uint32_t addr) {
    asm volatile("ldmatrix.sync.aligned.m8n8.x4.shared.b16 {%0,%1,%2,%3}, [%4];"
                 : "=r"(r0), "=r"(r1), "=r"(r2), "=r"(r3) : "r"(addr));
}
__device__ __forceinline__ void mma16816(float* d, uint32_t a0, uint32_t a1,
                                         uint32_t a2, uint32_t a3,
                                         uint32_t b0, uint32_t b1) {
    asm volatile(
        "mma.sync.aligned.m16n8k16.row.col.f32.bf16.bf16.f32 "
        "{%0,%1,%2,%3}, {%4,%5,%6,%7}, {%8,%9}, {%0,%1,%2,%3};"
        : "+f"(d[0]), "+f"(d[1]), "+f"(d[2]), "+f"(d[3])
        : "r"(a0), "r"(a1), "r"(a2), "r"(a3), "r"(b0), "r"(b1));
}

// ---------------- scatter: etype buckets, ntype buckets, dst histogram ----
__global__ void k_scatter_all(const int* __restrict__ etype,
                              const int* __restrict__ ntype,
                              const int* __restrict__ dst_idx,
                              int E, int M) {
    int t = blockIdx.x * blockDim.x + threadIdx.x;
    int lane = threadIdx.x & 31;
    unsigned actE = __ballot_sync(0xffffffffu, t < E);
    if (t < E) {
        int r = etype[t];
        unsigned m = __match_any_sync(actE, r);
        int leader = __ffs(m) - 1;
        int rank = __popc(m & ((1u << lane) - 1));
        int base = 0;
        if (lane == leader) base = atomicAdd(&g_cur[r], __popc(m));
        base = __shfl_sync(actE, base, leader);
        g_order[(size_t)r * E_MAX + base + rank] = t;
        atomicAdd(&g_dhist[dst_idx[t]], 1);
    }
    unsigned actM = __ballot_sync(0xffffffffu, t < M);
    if (t < M) {
        int r = ntype[t];
        unsigned m = __match_any_sync(actM, r);
        int leader = __ffs(m) - 1;
        int rank = __popc(m & ((1u << lane) - 1));
        int base = 0;
        if (lane == leader) base = atomicAdd(&g_ncur[r], __popc(m));
        base = __shfl_sync(actM, base, leader);
        g_norder[(size_t)r * M_MAX + base + rank] = t;
    }
}

// ---------------- single-block exclusive scan of g_dhist -> g_doff -------
__global__ void __launch_bounds__(1024, 1) k_scan_dst(int M) {
    const int tid = threadIdx.x;
    const int per = (M + 1023) / 1024;
    const int start = tid * per;
    const int end = min(start + per, M);
    int local = 0;
    for (int i = start; i < end; i++) local += g_dhist[i];
    __shared__ int wsum[32];
    int lane = tid & 31, w = tid >> 5;
    int v = local;
#pragma unroll
    for (int o = 1; o < 32; o <<= 1) {
        int u = __shfl_up_sync(0xffffffffu, v, o);
        if (lane >= o) v += u;
    }
    if (lane == 31) wsum[w] = v;
    __syncthreads();
    if (w == 0) {
        int s = wsum[lane];
#pragma unroll
        for (int o = 1; o < 32; o <<= 1) {
            int u = __shfl_up_sync(0xffffffffu, s, o);
            if (lane >= o) s += u;
        }
        wsum[lane] = s;
    }
    __syncthreads();
    int run = v - local + (w > 0 ? wsum[w - 1] : 0);
    for (int i = start; i < end; i++) { g_doff[i] = run; run += g_dhist[i]; }
}

__global__ void k_scatter_dst(const int* __restrict__ dst_idx, int E) {
    int e = blockIdx.x * blockDim.x + threadIdx.x;
    if (e < E) {
        int d = dst_idx[e];
        int p = atomicAdd(&g_dcur[d], 1);
        g_dorder[g_doff[d] + p] = e;
    }
}

// ---------------- weight transpose + bf16 hi/lo split (+ fused reset) ----
__global__ void k_wconv2(const float* __restrict__ Wq,
                         const float* __restrict__ Wk,
                         const float* __restrict__ Wv, int M) {
    const int which = blockIdx.z;      // 0=Q, 1=K, 2=V
    const int r = blockIdx.y;
    const int KD = (which == 0) ? IN_DIM : CAT_DIM;
    const int ntiles_n = OUT_DIM / 32;
    const int tile = blockIdx.x;
    const int kt = tile / ntiles_n;
    const int nt = tile - kt * ntiles_n;
    if (kt * 32 >= KD) {
        // reclaim out-of-range Q blocks (z==0, kt 4..4, 4 blocks x 256 thr)
        if (which == 0 && r == 0) {
            int t = (tile - 16) * 256 + threadIdx.y * 32 + threadIdx.x;
            for (int i = t; i < M; i += 4 * 256) { g_dhist[i] = 0; g_dcur[i] = 0; }
            if (t < R_TYPES) g_cur[t] = 0;
            if (t < T_TYPES) g_ncur[t] = 0;
        }
        return;
    }

    const float* W = (which == 0 ? Wq : which == 1 ? Wk : Wv)
                   + (size_t)r * KD * OUT_DIM;
    __nv_bfloat16* wh = (which == 0 ? g_wq_hi : which == 1 ? g_wk_hi : g_wv_hi)
                      + (size_t)r * OUT_DIM * KD;
    __nv_bfloat16* wl = (which == 0 ? g_wq_lo : which == 1 ? g_wk_lo : g_wv_lo)
                      + (size_t)r * OUT_DIM * KD;

    __shared__ float smt[32][33];
    const int tx = threadIdx.x, ty = threadIdx.y;  // 32 x 8
#pragma unroll
    for (int dy = 0; dy < 4; dy++) {
        int k = kt * 32 + ty + dy * 8;
        smt[ty + dy * 8][tx] = W[(size_t)k * OUT_DIM + nt * 32 + tx];
    }
    __syncthreads();
#pragma unroll
    for (int dy = 0; dy < 4; dy++) {
        int n = nt * 32 + ty + dy * 8;
        int k = kt * 32 + tx;
        float v = smt[tx][ty + dy * 8];
        __nv_bfloat16 h = __float2bfloat16(v);
        wh[(size_t)n * KD + k] = h;
        wl[(size_t)n * KD + k] = __float2bfloat16(v - __bfloat162float(h));
    }
}

// ---------------- fully fused QKV + logits kernel ----------------
#define SA  (CAT_DIM + 8)     // unified row stride (bf16 elems) = 168
#define SAB (SA * 2)          // 336 bytes

__global__ void __launch_bounds__(512, 1)
k_qkv(const float* __restrict__ src_h,
      const float* __restrict__ src_tw,
      const float* __restrict__ src_tb,
      const float* __restrict__ edge_h,
      const float* __restrict__ date,
      const int*   __restrict__ src_idx,
      const int*   __restrict__ dst_idx,
      const float* __restrict__ sg, const float* __restrict__ sb,
      const float* __restrict__ dg, const float* __restrict__ db)
{
    const int r = blockIdx.y;
    const int cnt = g_cur[r];
    const int tb = blockIdx.x * TILE_E;
    if (tb >= cnt) return;
    const size_t base = (size_t)r * E_MAX + tb;
    const int ne = min(TILE_E, cnt - tb);

    extern __shared__ __align__(16) char sm[];
    __nv_bfloat16* aH = (__nv_bfloat16*)sm;
    __nv_bfloat16* aL = aH + 128 * SA;
    __nv_bfloat16* bH = aL + 128 * SA;
    __nv_bfloat16* bL = bH + 128 * SA;
    __shared__ int so[TILE_E];

    const int tid = threadIdx.x, wid = tid >> 5, lane = tid & 31;
    if (tid < TILE_E) so[tid] = (tid < ne) ? g_order[base + tid] : 0;
    __syncthreads();

    // ---------- MLP-friendly fused LN staging: 8 rows per warp ----------
    auto stage_ln = [&](bool SRC) {
        const int NR = SRC ? 5 : 4;
        const float inv_kd = SRC ? (1.0f / CAT_DIM) : (1.0f / IN_DIM);
        const float* lng = SRC ? sg : dg;
        const float* lnb = SRC ? sb : db;
        int   eA[8]; int ndA[8]; float tA[8];
#pragma unroll
        for (int w8 = 0; w8 < 8; w8++) {
            int i = wid * 8 + w8;
            int e = so[i < ne ? i : 0];
            eA[w8] = e;
            ndA[w8] = SRC ? src_idx[e] : dst_idx[e];
            tA[w8] = date[e];
        }
        float xs[8][5];
#pragma unroll
        for (int w8 = 0; w8 < 8; w8++) {
            int nd = ndA[w8];
            xs[w8][0] = __sinf(src_tw[(size_t)nd * TD + lane] * tA[w8] +
                               src_tb[(size_t)nd * TD + lane]) *
                        src_h[(size_t)nd * IN_DIM + lane];
#pragma unroll
            for (int k = 1; k < 4; k++)
                xs[w8][k] = src_h[(size_t)nd * IN_DIM + lane + 32 * k];
            if (SRC) xs[w8][4] = edge_h[(size_t)eA[w8] * E_DIM + lane];
        }
        float mu[8], rstd[8];
#pragma unroll
        for (int w8 = 0; w8 < 8; w8++) {
            float s = 0.f;
            for (int k = 0; k < NR; k++) s += xs[w8][k];
#pragma unroll
            for (int o = 16; o > 0; o >>= 1) s += __shfl_xor_sync(0xffffffffu, s, o);
            mu[w8] = s * inv_kd;
        }
#pragma unroll
        for (int w8 = 0; w8 < 8; w8++) {
            float s = 0.f;
            for (int k = 0; k < NR; k++) { float d = xs[w8][k] - mu[w8]; s += d * d; }
#pragma unroll
            for (int o = 16; o > 0; o >>= 1) s += __shfl_xor_sync(0xffffffffu, s, o);
            rstd[w8] = rsqrtf(s * inv_kd + LN_EPS);
        }
#pragma unroll
        for (int w8 = 0; w8 < 8; w8++) {
            int i = wid * 8 + w8;
            __nv_bfloat16* rowH = aH + i * SA;
            __nv_bfloat16* rowL = aL + i * SA;
            bool valid = i < ne;
            for (int k = 0; k < NR; k++) {
                int j = lane + 32 * k;
                float y = valid ? (xs[w8][k] - mu[w8]) * rstd[w8] * lng[j] + lnb[j] : 0.f;
                __nv_bfloat16 h = __float2bfloat16(y);
                rowH[j] = h;
                rowL[j] = __float2bfloat16(y - __bfloat162float(h));
            }
        }
    };

    auto stage_B = [&](const __nv_bfloat16* wh, const __nv_bfloat16* wl, int U) {
        for (int idx = tid; idx < 128 * U; idx += 512) {
            int n = idx / U, u = idx - n * U;
            *(uint4*)((char*)bH + n * SAB + u * 16) = ((const uint4*)(wh + (size_t)n * (U * 8)))[u];
            *(uint4*)((char*)bL + n * SAB + u * 16) = ((const uint4*)(wl + (size_t)n * (U * 8)))[u];
        }
    };

    const int stripe = (wid >> 1) * 16;
    const int nhalf  = (wid & 1) * 64;

    const uint32_t aOffH = smem_u32(aH) + (uint32_t)(stripe + (lane & 15)) * SAB
                         + (uint32_t)(lane >> 4) * 16;
    const uint32_t aOffL = aOffH + (uint32_t)(128 * SAB);
    const int brow = ((lane >> 4) & 1) * 8 + (lane & 7);
    const int bko  = ((lane >> 3) & 1) * 16;
    const uint32_t bOffH = smem_u32(bH) + (uint32_t)(nhalf + brow) * SAB + bko;
    const uint32_t bOffL = bOffH + (uint32_t)(128 * SAB);

    float acc[8][4], kacc[8][4];

    // fused 3-product pass: per k-chunk load Ah/Al/Bh/Bl once, issue
    // hi*hi + hi*lo + lo*hi from registers (15 -> 10 LDSM per chunk)
    auto run3 = [&](float (*dst)[4], int nk) {
#pragma unroll
        for (int j = 0; j < 8; j++)
#pragma unroll
            for (int b = 0; b < 4; b++) dst[j][b] = 0.f;
#pragma unroll
        for (int ks = 0; ks < 10; ks++) {
            if (ks >= nk) break;
            uint32_t ah0, ah1, ah2, ah3, al0, al1, al2, al3;
            ldsm4(ah0, ah1, ah2, ah3, aOffH + ks * 32);
            ldsm4(al0, al1, al2, al3, aOffL + ks * 32);
#pragma unroll
            for (int tp = 0; tp < 4; tp++) {
                uint32_t bh0, bh1, bh2, bh3, bl0, bl1, bl2, bl3;
                ldsm4(bh0, bh1, bh2, bh3, bOffH + tp * 16 * SAB + ks * 32);
                ldsm4(bl0, bl1, bl2, bl3, bOffL + tp * 16 * SAB + ks * 32);
                mma16816(dst[2 * tp],     ah0, ah1, ah2, ah3, bh0, bh1);
                mma16816(dst[2 * tp + 1], ah0, ah1, ah2, ah3, bh2, bh3);
                mma16816(dst[2 * tp],     ah0, ah1, ah2, ah3, bl0, bl1);
                mma16816(dst[2 * tp + 1], ah0, ah1, ah2, ah3, bl2, bl3);
                mma16816(dst[2 * tp],     al0, al1, al2, al3, bh0, bh1);
                mma16816(dst[2 * tp + 1], al0, al1, al2, al3, bh2, bh3);
            }
        }
    };

    // ---- phase A: A_s + Wk -> K fragments (directly into kacc) ----
    stage_ln(true);
    stage_B(g_wk_hi + (size_t)r * OUT_DIM * CAT_DIM,
            g_wk_lo + (size_t)r * OUT_DIM * CAT_DIM, CAT_DIM / 8);
    __syncthreads();
    run3(kacc, CAT_DIM / 16);

    // ---- phase B: Wv -> V -> g_v ----
    __syncthreads();
    stage_B(g_wv_hi + (size_t)r * OUT_DIM * CAT_DIM,
            g_wv_lo + (size_t)r * OUT_DIM * CAT_DIM, CAT_DIM / 8);
    __syncthreads();
    run3(acc, CAT_DIM / 16);
    {
        int r0 = stripe + (lane >> 2);
        int c  = nhalf + (lane & 3) * 2;
        bool vA = r0 < ne, vB = (r0 + 8) < ne;
        size_t gA = vA ? (size_t)so[r0] * OUT_DIM : 0;
        size_t gB = vB ? (size_t)so[r0 + 8] * OUT_DIM : 0;
#pragma unroll
        for (int j = 0; j < 8; j++) {
            if (vA) *(float2*)&g_v[gA + c + j * 8] = make_float2(acc[j][0], acc[j][1]);
            if (vB) *(float2*)&g_v[gB + c + j * 8] = make_float2(acc[j][2], acc[j][3]);
        }
    }

    // ---- phase C: A_d + Wq -> Q fragments ----
    __syncthreads();
    stage_ln(false);
    stage_B(g_wq_hi + (size_t)r * OUT_DIM * IN_DIM,
            g_wq_lo + (size_t)r * OUT_DIM * IN_DIM, IN_DIM / 8);
    __syncthreads();
    run3(acc, IN_DIM / 16);

    // ---- logits from fragments: a[e][h] = (q.k)/sqrt(128) ----
    {
        int r0 = stripe + (lane >> 2);
        bool vA = r0 < ne, vB = (r0 + 8) < ne;
#pragma unroll
        for (int hl = 0; hl < 4; hl++) {
            float sA = 0.f, sB = 0.f;
#pragma unroll
            for (int jj = 0; jj < 2; jj++) {
                int j = 2 * hl + jj;
                sA += acc[j][0] * kacc[j][0] + acc[j][1] * kacc[j][1];
                sB += acc[j][2] * kacc[j][2] + acc[j][3] * kacc[j][3];
            }
            sA += __shfl_xor_sync(0xffffffffu, sA, 1);
            sA += __shfl_xor_sync(0xffffffffu, sA, 2);
            sB += __shfl_xor_sync(0xffffffffu, sB, 1);
            sB += __shfl_xor_sync(0xffffffffu, sB, 2);
            if ((lane & 3) == 0) {
                int h = (wid & 1) * 4 + hl;
                if (vA) g_a[(size_t)so[r0] * H_HEADS + h] =
                            sA * 0.08838834764831845f;
                if (vB) g_a[(size_t)so[r0 + 8] * H_HEADS + h] =
                            sB * 0.08838834764831845f;
            }
        }
    }
}

// ---------------- fused softmax + weighted V (warp per node) ----------
__global__ void k_attn2(int M)
{
    int warp = (blockIdx.x * blockDim.x + threadIdx.x) >> 5;
    int lane = threadIdx.x & 31;
    if (warp >= M) return;
    const int m = warp;
    const int beg = g_doff[m];
    const int cnt = g_dhist[m];
    const int h = lane >> 2;

    float amax = -1e30f, denom = 0.f;
    for (int i = 0; i < cnt; i++) {
        int e = g_dorder[beg + i];
        float a = g_a[(size_t)e * H_HEADS + h];
        float nmax = fmaxf(amax, a);
        denom = denom * __expf(amax - nmax) + __expf(a - nmax);
        amax = nmax;
    }
    float inv = (cnt > 0) ? 1.f / denom : 0.f;

    const int c0 = lane * 4;
    float4 acc = make_float4(0.f, 0.f, 0.f, 0.f);
    for (int i = 0; i < cnt; i++) {
        int e = g_dorder[beg + i];
        float a = g_a[(size_t)e * H_HEADS + h];
        float alpha = __expf(a - amax) * inv;
        float4 v = *(const float4*)&g_v[(size_t)e * OUT_DIM + c0];
        acc.x += v.x * alpha;
        acc.y += v.y * alpha;
        acc.z += v.z * alpha;
        acc.w += v.w * alpha;
    }
    *(float4*)&g_hacc[(size_t)m * OUT_DIM + c0] = acc;
}

// ---------------- typed output projection (tiled by ntype) -------------
__global__ void __launch_bounds__(256, 2)
k_out_t(const float* __restrict__ Wa,
        const float* __restrict__ h_bias,
        const float* __restrict__ skip,
        const float* __restrict__ src_h,
        float* __restrict__ out, int M)
{
    const int r = blockIdx.y;
    const int cnt = g_ncur[r];
    const int tbase = blockIdx.x * TILE_M;
    if (tbase >= cnt) return;
    const size_t base = (size_t)r * M_MAX + tbase;
    const int ne = min(TILE_M, cnt - tbase);

    extern __shared__ float smf[];
    float* Ws = smf;
    float* Ds = smf + OUT_DIM * OUT_DIM;
    const int DS = TILE_M + 4;
    __shared__ int no[TILE_M];

    const int tid = threadIdx.x;
    if (tid < TILE_M) no[tid] = (tid < ne) ? g_norder[base + tid] : 0;
    __syncthreads();

    {
        const float* W = Wa + (size_t)r * OUT_DIM * OUT_DIM;
        for (int idx = tid; idx < OUT_DIM * (OUT_DIM / 4); idx += 256)
            ((float4*)Ws)[idx] = ((const float4*)W)[idx];
    }
    for (int idx = tid; idx < TILE_M * OUT_DIM; idx += 256) {
        int m = idx >> 7;
        int i = idx & 127;
        Ds[i * DS + m] = (m < ne) ?
            g_hacc[(size_t)no[m] * OUT_DIM + i] + h_bias[(size_t)r * OUT_DIM + i] : 0.f;
    }
    __syncthreads();

    const int c0 = (tid & 31) * 4;
    const int m0 = (tid >> 5) * 8;
    ull acc[4][4];
#pragma unroll
    for (int p = 0; p < 4; p++)
#pragma unroll
        for (int b = 0; b < 4; b++) acc[p][b] = 0ull;

#pragma unroll 8
    for (int i = 0; i < OUT_DIM; i++) {
        float4 w = *(const float4*)&Ws[i * OUT_DIM + c0];
        ull wd0 = dup2(w.x), wd1 = dup2(w.y), wd2 = dup2(w.z), wd3 = dup2(w.w);
        ulonglong2 p0 = *(const ulonglong2*)&Ds[i * DS + m0];
        ulonglong2 p1 = *(const ulonglong2*)&Ds[i * DS + m0 + 4];
        ull de[4] = {p0.x, p0.y, p1.x, p1.y};
#pragma unroll
        for (int p = 0; p < 4; p++) {
            acc[p][0] = fma2(de[p], wd0, acc[p][0]);
            acc[p][1] = fma2(de[p], wd1, acc[p][1]);
            acc[p][2] = fma2(de[p], wd2, acc[p][2]);
            acc[p][3] = fma2(de[p], wd3, acc[p][3]);
        }
    }

    float gate = 1.f / (1.f + __expf(-skip[r]));
    float og = 1.f - gate;
#pragma unroll
    for (int p = 0; p < 4; p++) {
        float2 v0 = unpk(acc[p][0]);
        float2 v1 = unpk(acc[p][1]);
        float2 v2 = unpk(acc[p][2]);
        float2 v3 = unpk(acc[p][3]);
        int mA = m0 + 2 * p, mB = mA + 1;
        if (mA < ne) {
            size_t gm = (size_t)no[mA] * OUT_DIM + c0;
            float4 s = *(const float4*)&src_h[gm];
            *(float4*)&out[gm] = make_float4(v0.x * gate + s.x * og,
                                             v1.x * gate + s.y * og,
                                             v2.x * gate + s.z * og,
                                             v3.x * gate + s.w * og);
        }
        if (mB < ne) {
            size_t gm = (size_t)no[mB] * OUT_DIM + c0;
            float4 s = *(const float4*)&src_h[gm];
            *(float4*)&out[gm] = make_float4(v0.y * gate + s.x * og,
                                             v1.y * gate + s.y * og,
                                             v2.y * gate + s.z * og,
                                             v3.y * gate + s.w * og);
        }
    }
}

// ---------------- launch ----------------
extern "C" void kernel_launch(void* const* d_in, const int* in_sizes, int n_in,
                              void* d_out, int out_size)
{
    const float* src_h  = (const float*)d_in[0];
    const float* src_tw = (const float*)d_in[1];
    const float* src_tb = (const float*)d_in[2];
    const float* edge_h = (const float*)d_in[3];
    const float* date   = (const float*)d_in[4];
    const int*   src_idx = (const int*)d_in[5];
    const int*   dst_idx = (const int*)d_in[6];
    const int*   etype   = (const int*)d_in[7];
    const int*   ntype   = (const int*)d_in[8];
    const float* Wq = (const float*)d_in[9];
    const float* Wk = (const float*)d_in[10];
    const float* Wv = (const float*)d_in[11];
    const float* Wa = (const float*)d_in[12];
    const float* h_bias = (const float*)d_in[13];
    const float* skip   = (const float*)d_in[14];
    const float* sg = (const float*)d_in[15];
    const float* sb = (const float*)d_in[16];
    const float* dg = (const float*)d_in[17];
    const float* db = (const float*)d_in[18];
    float* out = (float*)d_out;

    const int E = in_sizes[4];
    const int M = in_sizes[8];

    const int SMF = 4 * 128 * SA * 2;  // 172032
    const int SMO = (OUT_DIM * OUT_DIM + OUT_DIM * (TILE_M + 4)) * 4;
    cudaFuncSetAttribute(k_qkv, cudaFuncAttributeMaxDynamicSharedMemorySize, SMF);
    cudaFuncSetAttribute(k_out_t, cudaFuncAttributeMaxDynamicSharedMemorySize, SMO);

    int mx = (E > M) ? E : M;
    {
        // wconv + fused reset (reclaimed early-return blocks)
        dim3 gw((CAT_DIM / 32) * (OUT_DIM / 32), R_TYPES, 3);
        k_wconv2<<<gw, dim3(32, 8)>>>(Wq, Wk, Wv, M);
    }
    k_scatter_all<<<(mx + 255) / 256, 256>>>(etype, ntype, dst_idx, E, M);
    k_scan_dst<<<1, 1024>>>(M);
    k_scatter_dst<<<(E + 255) / 256, 256>>>(dst_idx, E);
    dim3 gq((E + TILE_E - 1) / TILE_E, R_TYPES);
    k_qkv<<<gq, 512, SMF>>>(src_h, src_tw, src_tb, edge_h, date,
                            src_idx, dst_idx, sg, sb, dg, db);
    k_attn2<<<(M * 32 + 255) / 256, 256>>>(M);
    dim3 go((M + TILE_M - 1) / TILE_M, T_TYPES);
    k_out_t<<<go, 256, SMO>>>(Wa, h_bias, skip, src_h, out, M);
}

// round 14
// speedup vs baseline: 1.6812x; 1.0116x over previous
#include <cuda_runtime.h>
#include <cuda_bf16.h>
#include <math.h>
#include <stdint.h>

// ---------------- problem constants ----------------
#define IN_DIM   128
#define E_DIM    32
#define CAT_DIM  160
#define OUT_DIM  128
#define TD       32
#define H_HEADS  8
#define HS       16
#define R_TYPES  8
#define T_TYPES  4
#define LN_EPS   1e-5f
#define E_MAX    100000
#define M_MAX    10000
#define TILE_E   128
#define TILE_M   64

typedef unsigned long long ull;

// ---------------- device scratch ----------------
__device__ __nv_bfloat16 g_wq_hi[(size_t)R_TYPES * OUT_DIM * IN_DIM];
__device__ __nv_bfloat16 g_wq_lo[(size_t)R_TYPES * OUT_DIM * IN_DIM];
__device__ __nv_bfloat16 g_wk_hi[(size_t)R_TYPES * OUT_DIM * CAT_DIM];
__device__ __nv_bfloat16 g_wk_lo[(size_t)R_TYPES * OUT_DIM * CAT_DIM];
__device__ __nv_bfloat16 g_wv_hi[(size_t)R_TYPES * OUT_DIM * CAT_DIM];
__device__ __nv_bfloat16 g_wv_lo[(size_t)R_TYPES * OUT_DIM * CAT_DIM];

__device__ float    g_v[(size_t)E_MAX * OUT_DIM];
__device__ float    g_a[(size_t)E_MAX * H_HEADS];
__device__ float    g_hacc[(size_t)M_MAX * OUT_DIM];

__device__ int      g_cur[R_TYPES];
__device__ int      g_order[(size_t)R_TYPES * E_MAX];
__device__ int      g_ncur[T_TYPES];
__device__ int      g_norder[(size_t)T_TYPES * M_MAX];
__device__ int      g_dhist[M_MAX], g_doff[M_MAX], g_dcur[M_MAX];
__device__ int      g_dorder[E_MAX];

// ---------------- f32x2 packed-FMA helpers (k_out) ----------------
__device__ __forceinline__ ull fma2(ull a, ull b, ull c) {
    ull d;
    asm("fma.rn.f32x2 %0, %1, %2, %3;" : "=l"(d) : "l"(a), "l"(b), "l"(c));
    return d;
}
__device__ __forceinline__ ull dup2(float x) {
    ull d; asm("mov.b64 %0, {%1, %1};" : "=l"(d) : "f"(x)); return d;
}
__device__ __forceinline__ float2 unpk(ull v) {
    float2 f; asm("mov.b64 {%0, %1}, %2;" : "=f"(f.x), "=f"(f.y) : "l"(v)); return f;
}

// ---------------- mma.sync helpers ----------------
__device__ __forceinline__ uint32_t smem_u32(const void* p) {
    uint32_t a;
    asm("{ .reg .u64 t; cvta.to.shared.u64 t, %1; cvt.u32.u64 %0, t; }"
        : "=r"(a) : "l"(p));
    return a;
}
__device__ __forceinline__ void ldsm4(uint32_t& r0, uint32_t& r1, uint32_t& r2,
                                      uint32_t& r3, uint32_t addr) {
    asm volatile("ldmatrix.sync.aligned.m8n8.x4.shared.b16 {%0,%1,%2,%3}, [%4];"
                 : "=r"(r0), "=r"(r1), "=r"(r2), "=r"(r3) : "r"(addr));
}
__device__ __forceinline__ void mma16816(float* d, const uint32_t* a,
                                         uint32_t b0, uint32_t b1) {
    asm volatile(
        "mma.sync.aligned.m16n8k16.row.col.f32.bf16.bf16.f32 "
        "{%0,%1,%2,%3}, {%4,%5,%6,%7}, {%8,%9}, {%0,%1,%2,%3};"
        : "+f"(d[0]), "+f"(d[1]), "+f"(d[2]), "+f"(d[3])
        : "r"(a[0]), "r"(a[1]), "r"(a[2]), "r"(a[3]), "r"(b0), "r"(b1));
}

// ---------------- scatter: etype buckets, ntype buckets, dst histogram ----
__global__ void k_scatter_all(const int* __restrict__ etype,
                              const int* __restrict__ ntype,
                              const int* __restrict__ dst_idx,
                              int E, int M) {
    int t = blockIdx.x * blockDim.x + threadIdx.x;
    int lane = threadIdx.x & 31;
    unsigned actE = __ballot_sync(0xffffffffu, t < E);
    if (t < E) {
        int r = etype[t];
        unsigned m = __match_any_sync(actE, r);
        int leader = __ffs(m) - 1;
        int rank = __popc(m & ((1u << lane) - 1));
        int base = 0;
        if (lane == leader) base = atomicAdd(&g_cur[r], __popc(m));
        base = __shfl_sync(actE, base, leader);
        g_order[(size_t)r * E_MAX + base + rank] = t;
        atomicAdd(&g_dhist[dst_idx[t]], 1);
    }
    unsigned actM = __ballot_sync(0xffffffffu, t < M);
    if (t < M) {
        int r = ntype[t];
        unsigned m = __match_any_sync(actM, r);
        int leader = __ffs(m) - 1;
        int rank = __popc(m & ((1u << lane) - 1));
        int base = 0;
        if (lane == leader) base = atomicAdd(&g_ncur[r], __popc(m));
        base = __shfl_sync(actM, base, leader);
        g_norder[(size_t)r * M_MAX + base + rank] = t;
    }
}

// ---------------- single-block exclusive scan of g_dhist -> g_doff -------
__global__ void __launch_bounds__(1024, 1) k_scan_dst(int M) {
    const int tid = threadIdx.x;
    const int per = (M + 1023) / 1024;
    const int start = tid * per;
    const int end = min(start + per, M);
    int local = 0;
    for (int i = start; i < end; i++) local += g_dhist[i];
    __shared__ int wsum[32];
    int lane = tid & 31, w = tid >> 5;
    int v = local;
#pragma unroll
    for (int o = 1; o < 32; o <<= 1) {
        int u = __shfl_up_sync(0xffffffffu, v, o);
        if (lane >= o) v += u;
    }
    if (lane == 31) wsum[w] = v;
    __syncthreads();
    if (w == 0) {
        int s = wsum[lane];
#pragma unroll
        for (int o = 1; o < 32; o <<= 1) {
            int u = __shfl_up_sync(0xffffffffu, s, o);
            if (lane >= o) s += u;
        }
        wsum[lane] = s;
    }
    __syncthreads();
    int run = v - local + (w > 0 ? wsum[w - 1] : 0);
    for (int i = start; i < end; i++) { g_doff[i] = run; run += g_dhist[i]; }
}

__global__ void k_scatter_dst(const int* __restrict__ dst_idx, int E) {
    int e = blockIdx.x * blockDim.x + threadIdx.x;
    if (e < E) {
        int d = dst_idx[e];
        int p = atomicAdd(&g_dcur[d], 1);
        g_dorder[g_doff[d] + p] = e;
    }
}

// ---------------- weight transpose + bf16 hi/lo split (+ fused reset) ----
__global__ void k_wconv2(const float* __restrict__ Wq,
                         const float* __restrict__ Wk,
                         const float* __restrict__ Wv, int M) {
    const int which = blockIdx.z;      // 0=Q, 1=K, 2=V
    const int r = blockIdx.y;
    const int KD = (which == 0) ? IN_DIM : CAT_DIM;
    const int ntiles_n = OUT_DIM / 32;
    const int tile = blockIdx.x;
    const int kt = tile / ntiles_n;
    const int nt = tile - kt * ntiles_n;
    if (kt * 32 >= KD) {
        if (which == 0 && r == 0) {
            int t = (tile - 16) * 256 + threadIdx.y * 32 + threadIdx.x;
            for (int i = t; i < M; i += 4 * 256) { g_dhist[i] = 0; g_dcur[i] = 0; }
            if (t < R_TYPES) g_cur[t] = 0;
            if (t < T_TYPES) g_ncur[t] = 0;
        }
        return;
    }

    const float* W = (which == 0 ? Wq : which == 1 ? Wk : Wv)
                   + (size_t)r * KD * OUT_DIM;
    __nv_bfloat16* wh = (which == 0 ? g_wq_hi : which == 1 ? g_wk_hi : g_wv_hi)
                      + (size_t)r * OUT_DIM * KD;
    __nv_bfloat16* wl = (which == 0 ? g_wq_lo : which == 1 ? g_wk_lo : g_wv_lo)
                      + (size_t)r * OUT_DIM * KD;

    __shared__ float smt[32][33];
    const int tx = threadIdx.x, ty = threadIdx.y;  // 32 x 8
#pragma unroll
    for (int dy = 0; dy < 4; dy++) {
        int k = kt * 32 + ty + dy * 8;
        smt[ty + dy * 8][tx] = W[(size_t)k * OUT_DIM + nt * 32 + tx];
    }
    __syncthreads();
#pragma unroll
    for (int dy = 0; dy < 4; dy++) {
        int n = nt * 32 + ty + dy * 8;
        int k = kt * 32 + tx;
        float v = smt[tx][ty + dy * 8];
        __nv_bfloat16 h = __float2bfloat16(v);
        wh[(size_t)n * KD + k] = h;
        wl[(size_t)n * KD + k] = __float2bfloat16(v - __bfloat162float(h));
    }
}

// ---------------- fully fused QKV + logits kernel (32x32 warp tiles) ------
#define SA  (CAT_DIM + 8)     // unified row stride (bf16 elems) = 168
#define SAB (SA * 2)          // 336 bytes

__global__ void __launch_bounds__(512, 1)
k_qkv(const float* __restrict__ src_h,
      const float* __restrict__ src_tw,
      const float* __restrict__ src_tb,
      const float* __restrict__ edge_h,
      const float* __restrict__ date,
      const int*   __restrict__ src_idx,
      const int*   __restrict__ dst_idx,
      const float* __restrict__ sg, const float* __restrict__ sb,
      const float* __restrict__ dg, const float* __restrict__ db)
{
    const int r = blockIdx.y;
    const int cnt = g_cur[r];
    const int tb = blockIdx.x * TILE_E;
    if (tb >= cnt) return;
    const size_t base = (size_t)r * E_MAX + tb;
    const int ne = min(TILE_E, cnt - tb);

    extern __shared__ __align__(16) char sm[];
    __nv_bfloat16* aH = (__nv_bfloat16*)sm;
    __nv_bfloat16* aL = aH + 128 * SA;
    __nv_bfloat16* bH = aL + 128 * SA;
    __nv_bfloat16* bL = bH + 128 * SA;
    __shared__ int so[TILE_E];

    const int tid = threadIdx.x, wid = tid >> 5, lane = tid & 31;
    if (tid < TILE_E) so[tid] = (tid < ne) ? g_order[base + tid] : 0;
    __syncthreads();

    // ---------- MLP-friendly fused LN staging: 8 rows per warp ----------
    auto stage_ln = [&](bool SRC) {
        const int NR = SRC ? 5 : 4;
        const float inv_kd = SRC ? (1.0f / CAT_DIM) : (1.0f / IN_DIM);
        const float* lng = SRC ? sg : dg;
        const float* lnb = SRC ? sb : db;
        int   eA[8]; int ndA[8]; float tA[8];
#pragma unroll
        for (int w8 = 0; w8 < 8; w8++) {
            int i = wid * 8 + w8;
            int e = so[i < ne ? i : 0];
            eA[w8] = e;
            ndA[w8] = SRC ? src_idx[e] : dst_idx[e];
            tA[w8] = date[e];
        }
        float xs[8][5];
#pragma unroll
        for (int w8 = 0; w8 < 8; w8++) {
            int nd = ndA[w8];
            xs[w8][0] = __sinf(src_tw[(size_t)nd * TD + lane] * tA[w8] +
                               src_tb[(size_t)nd * TD + lane]) *
                        src_h[(size_t)nd * IN_DIM + lane];
#pragma unroll
            for (int k = 1; k < 4; k++)
                xs[w8][k] = src_h[(size_t)nd * IN_DIM + lane + 32 * k];
            if (SRC) xs[w8][4] = edge_h[(size_t)eA[w8] * E_DIM + lane];
        }
        float mu[8], rstd[8];
#pragma unroll
        for (int w8 = 0; w8 < 8; w8++) {
            float s = 0.f;
            for (int k = 0; k < NR; k++) s += xs[w8][k];
#pragma unroll
            for (int o = 16; o > 0; o >>= 1) s += __shfl_xor_sync(0xffffffffu, s, o);
            mu[w8] = s * inv_kd;
        }
#pragma unroll
        for (int w8 = 0; w8 < 8; w8++) {
            float s = 0.f;
            for (int k = 0; k < NR; k++) { float d = xs[w8][k] - mu[w8]; s += d * d; }
#pragma unroll
            for (int o = 16; o > 0; o >>= 1) s += __shfl_xor_sync(0xffffffffu, s, o);
            rstd[w8] = rsqrtf(s * inv_kd + LN_EPS);
        }
#pragma unroll
        for (int w8 = 0; w8 < 8; w8++) {
            int i = wid * 8 + w8;
            __nv_bfloat16* rowH = aH + i * SA;
            __nv_bfloat16* rowL = aL + i * SA;
            bool valid = i < ne;
            for (int k = 0; k < NR; k++) {
                int j = lane + 32 * k;
                float y = valid ? (xs[w8][k] - mu[w8]) * rstd[w8] * lng[j] + lnb[j] : 0.f;
                __nv_bfloat16 h = __float2bfloat16(y);
                rowH[j] = h;
                rowL[j] = __float2bfloat16(y - __bfloat162float(h));
            }
        }
    };

    auto stage_B = [&](const __nv_bfloat16* wh, const __nv_bfloat16* wl, int U) {
        for (int idx = tid; idx < 128 * U; idx += 512) {
            int n = idx / U, u = idx - n * U;
            *(uint4*)((char*)bH + n * SAB + u * 16) = ((const uint4*)(wh + (size_t)n * (U * 8)))[u];
            *(uint4*)((char*)bL + n * SAB + u * 16) = ((const uint4*)(wl + (size_t)n * (U * 8)))[u];
        }
    };

    // 32x32 warp tile: 4 row-stripes x 4 col-groups
    const int sr = (wid >> 2) * 32;     // row stripe base
    const int cg = (wid & 3) * 32;      // col group base

    // A ldsm addresses: two 16-row sets per plane
    const uint32_t aOffH0 = smem_u32(aH) + (uint32_t)(sr + (lane & 15)) * SAB
                          + (uint32_t)(lane >> 4) * 16;
    const uint32_t aOffH1 = aOffH0 + (uint32_t)(16 * SAB);
    const uint32_t aOffL0 = aOffH0 + (uint32_t)(128 * SAB);
    const uint32_t aOffL1 = aOffH1 + (uint32_t)(128 * SAB);
    // B ldsm addresses: two 16-col sets per plane
    const int brow = ((lane >> 4) & 1) * 8 + (lane & 7);
    const int bko  = ((lane >> 3) & 1) * 16;
    const uint32_t bOffH0 = smem_u32(bH) + (uint32_t)(cg + brow) * SAB + bko;
    const uint32_t bOffH1 = bOffH0 + (uint32_t)(16 * SAB);
    const uint32_t bOffL0 = bOffH0 + (uint32_t)(128 * SAB);
    const uint32_t bOffL1 = bOffH1 + (uint32_t)(128 * SAB);

    float acc[8][4], kacc[8][4];   // [rh*4 + co][4]

    // fused 3-product pass, 8 LDSM per k-chunk (A:4, B:4)
    auto run3 = [&](float (*dst)[4], int nk) {
#pragma unroll
        for (int j = 0; j < 8; j++)
#pragma unroll
            for (int b = 0; b < 4; b++) dst[j][b] = 0.f;
#pragma unroll
        for (int ks = 0; ks < 10; ks++) {
            if (ks >= nk) break;
            uint32_t ah0[4], ah1[4], al0[4], al1[4];
            ldsm4(ah0[0], ah0[1], ah0[2], ah0[3], aOffH0 + ks * 32);
            ldsm4(ah1[0], ah1[1], ah1[2], ah1[3], aOffH1 + ks * 32);
            ldsm4(al0[0], al0[1], al0[2], al0[3], aOffL0 + ks * 32);
            ldsm4(al1[0], al1[1], al1[2], al1[3], aOffL1 + ks * 32);
            uint32_t bh0[4], bh1[4], bl0[4], bl1[4];
            ldsm4(bh0[0], bh0[1], bh0[2], bh0[3], bOffH0 + ks * 32);
            ldsm4(bh1[0], bh1[1], bh1[2], bh1[3], bOffH1 + ks * 32);
            ldsm4(bl0[0], bl0[1], bl0[2], bl0[3], bOffL0 + ks * 32);
            ldsm4(bl1[0], bl1[1], bl1[2], bl1[3], bOffL1 + ks * 32);
#pragma unroll
            for (int rh = 0; rh < 2; rh++) {
                const uint32_t* Ah = rh ? ah1 : ah0;
                const uint32_t* Al = rh ? al1 : al0;
                // co 0: bh0/bl0 pair (b0,b1); co 1: (b2,b3); co 2/3 from set1
                mma16816(dst[rh * 4 + 0], Ah, bh0[0], bh0[1]);
                mma16816(dst[rh * 4 + 0], Ah, bl0[0], bl0[1]);
                mma16816(dst[rh * 4 + 0], Al, bh0[0], bh0[1]);
                mma16816(dst[rh * 4 + 1], Ah, bh0[2], bh0[3]);
                mma16816(dst[rh * 4 + 1], Ah, bl0[2], bl0[3]);
                mma16816(dst[rh * 4 + 1], Al, bh0[2], bh0[3]);
                mma16816(dst[rh * 4 + 2], Ah, bh1[0], bh1[1]);
                mma16816(dst[rh * 4 + 2], Ah, bl1[0], bl1[1]);
                mma16816(dst[rh * 4 + 2], Al, bh1[0], bh1[1]);
                mma16816(dst[rh * 4 + 3], Ah, bh1[2], bh1[3]);
                mma16816(dst[rh * 4 + 3], Ah, bl1[2], bl1[3]);
                mma16816(dst[rh * 4 + 3], Al, bh1[2], bh1[3]);
            }
        }
    };

    // ---- phase A: A_s + Wk -> K fragments (directly into kacc) ----
    stage_ln(true);
    stage_B(g_wk_hi + (size_t)r * OUT_DIM * CAT_DIM,
            g_wk_lo + (size_t)r * OUT_DIM * CAT_DIM, CAT_DIM / 8);
    __syncthreads();
    run3(kacc, CAT_DIM / 16);

    // ---- phase B: Wv -> V -> g_v ----
    __syncthreads();
    stage_B(g_wv_hi + (size_t)r * OUT_DIM * CAT_DIM,
            g_wv_lo + (size_t)r * OUT_DIM * CAT_DIM, CAT_DIM / 8);
    __syncthreads();
    run3(acc, CAT_DIM / 16);
    {
#pragma unroll
        for (int rh = 0; rh < 2; rh++) {
            int r0 = sr + rh * 16 + (lane >> 2);
            bool vA = r0 < ne, vB = (r0 + 8) < ne;
            size_t gA = vA ? (size_t)so[r0] * OUT_DIM : 0;
            size_t gB = vB ? (size_t)so[r0 + 8] * OUT_DIM : 0;
#pragma unroll
            for (int co = 0; co < 4; co++) {
                int c = cg + co * 8 + (lane & 3) * 2;
                int j = rh * 4 + co;
                if (vA) *(float2*)&g_v[gA + c] = make_float2(acc[j][0], acc[j][1]);
                if (vB) *(float2*)&g_v[gB + c] = make_float2(acc[j][2], acc[j][3]);
            }
        }
    }

    // ---- phase C: A_d + Wq -> Q fragments ----
    __syncthreads();
    stage_ln(false);
    stage_B(g_wq_hi + (size_t)r * OUT_DIM * IN_DIM,
            g_wq_lo + (size_t)r * OUT_DIM * IN_DIM, IN_DIM / 8);
    __syncthreads();
    run3(acc, IN_DIM / 16);

    // ---- logits from fragments: a[e][h] = (q.k)/sqrt(128) ----
    {
#pragma unroll
        for (int rh = 0; rh < 2; rh++) {
            int r0 = sr + rh * 16 + (lane >> 2);
            bool vA = r0 < ne, vB = (r0 + 8) < ne;
#pragma unroll
            for (int hl = 0; hl < 2; hl++) {
                float sA = 0.f, sB = 0.f;
#pragma unroll
                for (int cc = 0; cc < 2; cc++) {
                    int j = rh * 4 + 2 * hl + cc;
                    sA += acc[j][0] * kacc[j][0] + acc[j][1] * kacc[j][1];
                    sB += acc[j][2] * kacc[j][2] + acc[j][3] * kacc[j][3];
                }
                sA += __shfl_xor_sync(0xffffffffu, sA, 1);
                sA += __shfl_xor_sync(0xffffffffu, sA, 2);
                sB += __shfl_xor_sync(0xffffffffu, sB, 1);
                sB += __shfl_xor_sync(0xffffffffu, sB, 2);
                if ((lane & 3) == 0) {
                    int h = (wid & 3) * 2 + hl;
                    if (vA) g_a[(size_t)so[r0] * H_HEADS + h] =
                                sA * 0.08838834764831845f;
                    if (vB) g_a[(size_t)so[r0 + 8] * H_HEADS + h] =
                                sB * 0.08838834764831845f;
                }
            }
        }
    }
}

// ---------------- fused softmax + weighted V (warp per node) ----------
__global__ void k_attn2(int M)
{
    int warp = (blockIdx.x * blockDim.x + threadIdx.x) >> 5;
    int lane = threadIdx.x & 31;
    if (warp >= M) return;
    const int m = warp;
    const int beg = g_doff[m];
    const int cnt = g_dhist[m];
    const int h = lane >> 2;

    float amax = -1e30f, denom = 0.f;
    for (int i = 0; i < cnt; i++) {
        int e = g_dorder[beg + i];
        float a = g_a[(size_t)e * H_HEADS + h];
        float nmax = fmaxf(amax, a);
        denom = denom * __expf(amax - nmax) + __expf(a - nmax);
        amax = nmax;
    }
    float inv = (cnt > 0) ? 1.f / denom : 0.f;

    const int c0 = lane * 4;
    float4 acc = make_float4(0.f, 0.f, 0.f, 0.f);
    for (int i = 0; i < cnt; i++) {
        int e = g_dorder[beg + i];
        float a = g_a[(size_t)e * H_HEADS + h];
        float alpha = __expf(a - amax) * inv;
        float4 v = *(const float4*)&g_v[(size_t)e * OUT_DIM + c0];
        acc.x += v.x * alpha;
        acc.y += v.y * alpha;
        acc.z += v.z * alpha;
        acc.w += v.w * alpha;
    }
    *(float4*)&g_hacc[(size_t)m * OUT_DIM + c0] = acc;
}

// ---------------- typed output projection (tiled by ntype) -------------
__global__ void __launch_bounds__(256, 2)
k_out_t(const float* __restrict__ Wa,
        const float* __restrict__ h_bias,
        const float* __restrict__ skip,
        const float* __restrict__ src_h,
        float* __restrict__ out, int M)
{
    const int r = blockIdx.y;
    const int cnt = g_ncur[r];
    const int tbase = blockIdx.x * TILE_M;
    if (tbase >= cnt) return;
    const size_t base = (size_t)r * M_MAX + tbase;
    const int ne = min(TILE_M, cnt - tbase);

    extern __shared__ float smf[];
    float* Ws = smf;
    float* Ds = smf + OUT_DIM * OUT_DIM;
    const int DS = TILE_M + 4;
    __shared__ int no[TILE_M];

    const int tid = threadIdx.x;
    if (tid < TILE_M) no[tid] = (tid < ne) ? g_norder[base + tid] : 0;
    __syncthreads();

    {
        const float* W = Wa + (size_t)r * OUT_DIM * OUT_DIM;
        for (int idx = tid; idx < OUT_DIM * (OUT_DIM / 4); idx += 256)
            ((float4*)Ws)[idx] = ((const float4*)W)[idx];
    }
    for (int idx = tid; idx < TILE_M * OUT_DIM; idx += 256) {
        int m = idx >> 7;
        int i = idx & 127;
        Ds[i * DS + m] = (m < ne) ?
            g_hacc[(size_t)no[m] * OUT_DIM + i] + h_bias[(size_t)r * OUT_DIM + i] : 0.f;
    }
    __syncthreads();

    const int c0 = (tid & 31) * 4;
    const int m0 = (tid >> 5) * 8;
    ull acc[4][4];
#pragma unroll
    for (int p = 0; p < 4; p++)
#pragma unroll
        for (int b = 0; b < 4; b++) acc[p][b] = 0ull;

#pragma unroll 8
    for (int i = 0; i < OUT_DIM; i++) {
        float4 w = *(const float4*)&Ws[i * OUT_DIM + c0];
        ull wd0 = dup2(w.x), wd1 = dup2(w.y), wd2 = dup2(w.z), wd3 = dup2(w.w);
        ulonglong2 p0 = *(const ulonglong2*)&Ds[i * DS + m0];
        ulonglong2 p1 = *(const ulonglong2*)&Ds[i * DS + m0 + 4];
        ull de[4] = {p0.x, p0.y, p1.x, p1.y};
#pragma unroll
        for (int p = 0; p < 4; p++) {
            acc[p][0] = fma2(de[p], wd0, acc[p][0]);
            acc[p][1] = fma2(de[p], wd1, acc[p][1]);
            acc[p][2] = fma2(de[p], wd2, acc[p][2]);
            acc[p][3] = fma2(de[p], wd3, acc[p][3]);
        }
    }

    float gate = 1.f / (1.f + __expf(-skip[r]));
    float og = 1.f - gate;
#pragma unroll
    for (int p = 0; p < 4; p++) {
        float2 v0 = unpk(acc[p][0]);
        float2 v1 = unpk(acc[p][1]);
        float2 v2 = unpk(acc[p][2]);
        float2 v3 = unpk(acc[p][3]);
        int mA = m0 + 2 * p, mB = mA + 1;
        if (mA < ne) {
            size_t gm = (size_t)no[mA] * OUT_DIM + c0;
            float4 s = *(const float4*)&src_h[gm];
            *(float4*)&out[gm] = make_float4(v0.x * gate + s.x * og,
                                             v1.x * gate + s.y * og,
                                             v2.x * gate + s.z * og,
                                             v3.x * gate + s.w * og);
        }
        if (mB < ne) {
            size_t gm = (size_t)no[mB] * OUT_DIM + c0;
            float4 s = *(const float4*)&src_h[gm];
            *(float4*)&out[gm] = make_float4(v0.y * gate + s.x * og,
                                             v1.y * gate + s.y * og,
                                             v2.y * gate + s.z * og,
                                             v3.y * gate + s.w * og);
        }
    }
}

// ---------------- launch ----------------
extern "C" void kernel_launch(void* const* d_in, const int* in_sizes, int n_in,
                              void* d_out, int out_size)
{
    const float* src_h  = (const float*)d_in[0];
    const float* src_tw = (const float*)d_in[1];
    const float* src_tb = (const float*)d_in[2];
    const float* edge_h = (const float*)d_in[3];
    const float* date   = (const float*)d_in[4];
    const int*   src_idx = (const int*)d_in[5];
    const int*   dst_idx = (const int*)d_in[6];
    const int*   etype   = (const int*)d_in[7];
    const int*   ntype   = (const int*)d_in[8];
    const float* Wq = (const float*)d_in[9];
    const float* Wk = (const float*)d_in[10];
    const float* Wv = (const float*)d_in[11];
    const float* Wa = (const float*)d_in[12];
    const float* h_bias = (const float*)d_in[13];
    const float* skip   = (const float*)d_in[14];
    const float* sg = (const float*)d_in[15];
    const float* sb = (const float*)d_in[16];
    const float* dg = (const float*)d_in[17];
    const float* db = (const float*)d_in[18];
    float* out = (float*)d_out;

    const int E = in_sizes[4];
    const int M = in_sizes[8];

    const int SMF = 4 * 128 * SA * 2;  // 172032
    const int SMO = (OUT_DIM * OUT_DIM + OUT_DIM * (TILE_M + 4)) * 4;
    cudaFuncSetAttribute(k_qkv, cudaFuncAttributeMaxDynamicSharedMemorySize, SMF);
    cudaFuncSetAttribute(k_out_t, cudaFuncAttributeMaxDynamicSharedMemorySize, SMO);

    int mx = (E > M) ? E : M;
    {
        dim3 gw((CAT_DIM / 32) * (OUT_DIM / 32), R_TYPES, 3);
        k_wconv2<<<gw, dim3(32, 8)>>>(Wq, Wk, Wv, M);
    }
    k_scatter_all<<<(mx + 255) / 256, 256>>>(etype, ntype, dst_idx, E, M);
    k_scan_dst<<<1, 1024>>>(M);
    k_scatter_dst<<<(E + 255) / 256, 256>>>(dst_idx, E);
    dim3 gq((E + TILE_E - 1) / TILE_E, R_TYPES);
    k_qkv<<<gq, 512, SMF>>>(src_h, src_tw, src_tb, edge_h, date,
                            src_idx, dst_idx, sg, sb, dg, db);
    k_attn2<<<(M * 32 + 255) / 256, 256>>>(M);
    dim3 go((M + TILE_M - 1) / TILE_M, T_TYPES);
    k_out_t<<<go, 256, SMO>>>(Wa, h_bias, skip, src_h, out, M);
}

// round 15
// speedup vs baseline: 1.7980x; 1.0695x over previous
#include <cuda_runtime.h>
#include <cuda_fp16.h>
#include <math.h>
#include <stdint.h>

// ---------------- problem constants ----------------
#define IN_DIM   128
#define E_DIM    32
#define CAT_DIM  160
#define OUT_DIM  128
#define TD       32
#define H_HEADS  8
#define HS       16
#define R_TYPES  8
#define T_TYPES  4
#define LN_EPS   1e-5f
#define E_MAX    100000
#define M_MAX    10000
#define TILE_E   128
#define TILE_M   64

typedef unsigned long long ull;

// ---------------- device scratch ----------------
// weights: single fp16 plane (error 2^-12, inside the 1e-3 budget)
__device__ __half g_wq_h[(size_t)R_TYPES * OUT_DIM * IN_DIM];
__device__ __half g_wk_h[(size_t)R_TYPES * OUT_DIM * CAT_DIM];
__device__ __half g_wv_h[(size_t)R_TYPES * OUT_DIM * CAT_DIM];

__device__ float    g_v[(size_t)E_MAX * OUT_DIM];
__device__ float    g_a[(size_t)E_MAX * H_HEADS];
__device__ float    g_hacc[(size_t)M_MAX * OUT_DIM];

__device__ int      g_cur[R_TYPES];
__device__ int      g_order[(size_t)R_TYPES * E_MAX];
__device__ int      g_ncur[T_TYPES];
__device__ int      g_norder[(size_t)T_TYPES * M_MAX];
__device__ int      g_dhist[M_MAX], g_doff[M_MAX], g_dcur[M_MAX];
__device__ int      g_dorder[E_MAX];

// ---------------- f32x2 packed-FMA helpers (k_out) ----------------
__device__ __forceinline__ ull fma2(ull a, ull b, ull c) {
    ull d;
    asm("fma.rn.f32x2 %0, %1, %2, %3;" : "=l"(d) : "l"(a), "l"(b), "l"(c));
    return d;
}
__device__ __forceinline__ ull dup2(float x) {
    ull d; asm("mov.b64 %0, {%1, %1};" : "=l"(d) : "f"(x)); return d;
}
__device__ __forceinline__ float2 unpk(ull v) {
    float2 f; asm("mov.b64 {%0, %1}, %2;" : "=f"(f.x), "=f"(f.y) : "l"(v)); return f;
}

// ---------------- mma.sync helpers ----------------
__device__ __forceinline__ uint32_t smem_u32(const void* p) {
    uint32_t a;
    asm("{ .reg .u64 t; cvta.to.shared.u64 t, %1; cvt.u32.u64 %0, t; }"
        : "=r"(a) : "l"(p));
    return a;
}
__device__ __forceinline__ void ldsm4(uint32_t& r0, uint32_t& r1, uint32_t& r2,
                                      uint32_t& r3, uint32_t addr) {
    asm volatile("ldmatrix.sync.aligned.m8n8.x4.shared.b16 {%0,%1,%2,%3}, [%4];"
                 : "=r"(r0), "=r"(r1), "=r"(r2), "=r"(r3) : "r"(addr));
}
__device__ __forceinline__ void mma16816(float* d, const uint32_t* a,
                                         uint32_t b0, uint32_t b1) {
    asm volatile(
        "mma.sync.aligned.m16n8k16.row.col.f32.f16.f16.f32 "
        "{%0,%1,%2,%3}, {%4,%5,%6,%7}, {%8,%9}, {%0,%1,%2,%3};"
        : "+f"(d[0]), "+f"(d[1]), "+f"(d[2]), "+f"(d[3])
        : "r"(a[0]), "r"(a[1]), "r"(a[2]), "r"(a[3]), "r"(b0), "r"(b1));
}

// ---------------- scatter: etype buckets, ntype buckets, dst histogram ----
__global__ void k_scatter_all(const int* __restrict__ etype,
                              const int* __restrict__ ntype,
                              const int* __restrict__ dst_idx,
                              int E, int M) {
    int t = blockIdx.x * blockDim.x + threadIdx.x;
    int lane = threadIdx.x & 31;
    unsigned actE = __ballot_sync(0xffffffffu, t < E);
    if (t < E) {
        int r = etype[t];
        unsigned m = __match_any_sync(actE, r);
        int leader = __ffs(m) - 1;
        int rank = __popc(m & ((1u << lane) - 1));
        int base = 0;
        if (lane == leader) base = atomicAdd(&g_cur[r], __popc(m));
        base = __shfl_sync(actE, base, leader);
        g_order[(size_t)r * E_MAX + base + rank] = t;
        atomicAdd(&g_dhist[dst_idx[t]], 1);
    }
    unsigned actM = __ballot_sync(0xffffffffu, t < M);
    if (t < M) {
        int r = ntype[t];
        unsigned m = __match_any_sync(actM, r);
        int leader = __ffs(m) - 1;
        int rank = __popc(m & ((1u << lane) - 1));
        int base = 0;
        if (lane == leader) base = atomicAdd(&g_ncur[r], __popc(m));
        base = __shfl_sync(actM, base, leader);
        g_norder[(size_t)r * M_MAX + base + rank] = t;
    }
}

// ---------------- single-block exclusive scan of g_dhist -> g_doff -------
__global__ void __launch_bounds__(1024, 1) k_scan_dst(int M) {
    const int tid = threadIdx.x;
    const int per = (M + 1023) / 1024;
    const int start = tid * per;
    const int end = min(start + per, M);
    int local = 0;
    for (int i = start; i < end; i++) local += g_dhist[i];
    __shared__ int wsum[32];
    int lane = tid & 31, w = tid >> 5;
    int v = local;
#pragma unroll
    for (int o = 1; o < 32; o <<= 1) {
        int u = __shfl_up_sync(0xffffffffu, v, o);
        if (lane >= o) v += u;
    }
    if (lane == 31) wsum[w] = v;
    __syncthreads();
    if (w == 0) {
        int s = wsum[lane];
#pragma unroll
        for (int o = 1; o < 32; o <<= 1) {
            int u = __shfl_up_sync(0xffffffffu, s, o);
            if (lane >= o) s += u;
        }
        wsum[lane] = s;
    }
    __syncthreads();
    int run = v - local + (w > 0 ? wsum[w - 1] : 0);
    for (int i = start; i < end; i++) { g_doff[i] = run; run += g_dhist[i]; }
}

__global__ void k_scatter_dst(const int* __restrict__ dst_idx, int E) {
    int e = blockIdx.x * blockDim.x + threadIdx.x;
    if (e < E) {
        int d = dst_idx[e];
        int p = atomicAdd(&g_dcur[d], 1);
        g_dorder[g_doff[d] + p] = e;
    }
}

// ---------------- weight transpose + fp16 convert (+ fused reset) --------
__global__ void k_wconv2(const float* __restrict__ Wq,
                         const float* __restrict__ Wk,
                         const float* __restrict__ Wv, int M) {
    const int which = blockIdx.z;      // 0=Q, 1=K, 2=V
    const int r = blockIdx.y;
    const int KD = (which == 0) ? IN_DIM : CAT_DIM;
    const int ntiles_n = OUT_DIM / 32;
    const int tile = blockIdx.x;
    const int kt = tile / ntiles_n;
    const int nt = tile - kt * ntiles_n;
    if (kt * 32 >= KD) {
        if (which == 0 && r == 0) {
            int t = (tile - 16) * 256 + threadIdx.y * 32 + threadIdx.x;
            for (int i = t; i < M; i += 4 * 256) { g_dhist[i] = 0; g_dcur[i] = 0; }
            if (t < R_TYPES) g_cur[t] = 0;
            if (t < T_TYPES) g_ncur[t] = 0;
        }
        return;
    }

    const float* W = (which == 0 ? Wq : which == 1 ? Wk : Wv)
                   + (size_t)r * KD * OUT_DIM;
    __half* wh = (which == 0 ? g_wq_h : which == 1 ? g_wk_h : g_wv_h)
               + (size_t)r * OUT_DIM * KD;

    __shared__ float smt[32][33];
    const int tx = threadIdx.x, ty = threadIdx.y;  // 32 x 8
#pragma unroll
    for (int dy = 0; dy < 4; dy++) {
        int k = kt * 32 + ty + dy * 8;
        smt[ty + dy * 8][tx] = W[(size_t)k * OUT_DIM + nt * 32 + tx];
    }
    __syncthreads();
#pragma unroll
    for (int dy = 0; dy < 4; dy++) {
        int n = nt * 32 + ty + dy * 8;
        int k = kt * 32 + tx;
        wh[(size_t)n * KD + k] = __float2half_rn(smt[tx][ty + dy * 8]);
    }
}

// ---------------- fully fused QKV + logits kernel (32x32 warp tiles) ------
// A = LN output as fp16 hi/lo split (exact to ~2^-24); B = fp16 weights.
// 2 MMA passes per product: A_hi*B + A_lo*B.
#define SA  (CAT_DIM + 8)     // unified row stride (fp16 elems) = 168
#define SAB (SA * 2)          // 336 bytes

__global__ void __launch_bounds__(512, 1)
k_qkv(const float* __restrict__ src_h,
      const float* __restrict__ src_tw,
      const float* __restrict__ src_tb,
      const float* __restrict__ edge_h,
      const float* __restrict__ date,
      const int*   __restrict__ src_idx,
      const int*   __restrict__ dst_idx,
      const float* __restrict__ sg, const float* __restrict__ sb,
      const float* __restrict__ dg, const float* __restrict__ db)
{
    const int r = blockIdx.y;
    const int cnt = g_cur[r];
    const int tb = blockIdx.x * TILE_E;
    if (tb >= cnt) return;
    const size_t base = (size_t)r * E_MAX + tb;
    const int ne = min(TILE_E, cnt - tb);

    extern __shared__ __align__(16) char sm[];
    __half* aH = (__half*)sm;
    __half* aL = aH + 128 * SA;
    __half* bF = aL + 128 * SA;
    __shared__ int so[TILE_E];

    const int tid = threadIdx.x, wid = tid >> 5, lane = tid & 31;
    if (tid < TILE_E) so[tid] = (tid < ne) ? g_order[base + tid] : 0;
    __syncthreads();

    // ---------- fused LN staging: 2 batches of 4 rows per warp ----------
    // (reduced in-flight registers vs 8-row batch; MLP still ~20 loads)
    auto stage_ln = [&](bool SRC) {
        const int NR = SRC ? 5 : 4;
        const float inv_kd = SRC ? (1.0f / CAT_DIM) : (1.0f / IN_DIM);
        const float* lng = SRC ? sg : dg;
        const float* lnb = SRC ? sb : db;
#pragma unroll
        for (int half = 0; half < 2; half++) {
            int eA[4]; int ndA[4]; float tA[4];
#pragma unroll
            for (int b4 = 0; b4 < 4; b4++) {
                int i = wid * 8 + half * 4 + b4;
                int e = so[i < ne ? i : 0];
                eA[b4] = e;
                ndA[b4] = SRC ? src_idx[e] : dst_idx[e];
                tA[b4] = date[e];
            }
            float xs[4][5];
#pragma unroll
            for (int b4 = 0; b4 < 4; b4++) {
                int nd = ndA[b4];
                xs[b4][0] = __sinf(src_tw[(size_t)nd * TD + lane] * tA[b4] +
                                   src_tb[(size_t)nd * TD + lane]) *
                            src_h[(size_t)nd * IN_DIM + lane];
#pragma unroll
                for (int k = 1; k < 4; k++)
                    xs[b4][k] = src_h[(size_t)nd * IN_DIM + lane + 32 * k];
                if (SRC) xs[b4][4] = edge_h[(size_t)eA[b4] * E_DIM + lane];
            }
            float mu[4], rstd[4];
#pragma unroll
            for (int b4 = 0; b4 < 4; b4++) {
                float s = 0.f;
                for (int k = 0; k < NR; k++) s += xs[b4][k];
#pragma unroll
                for (int o = 16; o > 0; o >>= 1) s += __shfl_xor_sync(0xffffffffu, s, o);
                mu[b4] = s * inv_kd;
            }
#pragma unroll
            for (int b4 = 0; b4 < 4; b4++) {
                float s = 0.f;
                for (int k = 0; k < NR; k++) { float d = xs[b4][k] - mu[b4]; s += d * d; }
#pragma unroll
                for (int o = 16; o > 0; o >>= 1) s += __shfl_xor_sync(0xffffffffu, s, o);
                rstd[b4] = rsqrtf(s * inv_kd + LN_EPS);
            }
#pragma unroll
            for (int b4 = 0; b4 < 4; b4++) {
                int i = wid * 8 + half * 4 + b4;
                __half* rowH = aH + i * SA;
                __half* rowL = aL + i * SA;
                bool valid = i < ne;
                for (int k = 0; k < NR; k++) {
                    int j = lane + 32 * k;
                    float y = valid ? (xs[b4][k] - mu[b4]) * rstd[b4] * lng[j] + lnb[j] : 0.f;
                    __half h = __float2half_rn(y);
                    rowH[j] = h;
                    rowL[j] = __float2half_rn(y - __half2float(h));
                }
            }
        }
    };

    auto stage_B = [&](const __half* wh, int U) {
        for (int idx = tid; idx < 128 * U; idx += 512) {
            int n = idx / U, u = idx - n * U;
            *(uint4*)((char*)bF + n * SAB + u * 16) = ((const uint4*)(wh + (size_t)n * (U * 8)))[u];
        }
    };

    // 32x32 warp tile: 4 row-stripes x 4 col-groups
    const int sr = (wid >> 2) * 32;
    const int cg = (wid & 3) * 32;

    const uint32_t aOffH0 = smem_u32(aH) + (uint32_t)(sr + (lane & 15)) * SAB
                          + (uint32_t)(lane >> 4) * 16;
    const uint32_t aOffH1 = aOffH0 + (uint32_t)(16 * SAB);
    const uint32_t aOffL0 = aOffH0 + (uint32_t)(128 * SAB);
    const uint32_t aOffL1 = aOffH1 + (uint32_t)(128 * SAB);
    const int brow = ((lane >> 4) & 1) * 8 + (lane & 7);
    const int bko  = ((lane >> 3) & 1) * 16;
    const uint32_t bOff0 = smem_u32(bF) + (uint32_t)(cg + brow) * SAB + bko;
    const uint32_t bOff1 = bOff0 + (uint32_t)(16 * SAB);

    float acc[8][4], kacc[8][4];   // [rh*4 + co][4]

    // 2-pass product (A_hi*B + A_lo*B), 6 LDSM + 16 HMMA per k-chunk
    auto run2 = [&](float (*dst)[4], int nk) {
#pragma unroll
        for (int j = 0; j < 8; j++)
#pragma unroll
            for (int b = 0; b < 4; b++) dst[j][b] = 0.f;
#pragma unroll
        for (int ks = 0; ks < 10; ks++) {
            if (ks >= nk) break;
            uint32_t ah0[4], ah1[4], al0[4], al1[4];
            ldsm4(ah0[0], ah0[1], ah0[2], ah0[3], aOffH0 + ks * 32);
            ldsm4(ah1[0], ah1[1], ah1[2], ah1[3], aOffH1 + ks * 32);
            ldsm4(al0[0], al0[1], al0[2], al0[3], aOffL0 + ks * 32);
            ldsm4(al1[0], al1[1], al1[2], al1[3], aOffL1 + ks * 32);
            uint32_t b0[4], b1[4];
            ldsm4(b0[0], b0[1], b0[2], b0[3], bOff0 + ks * 32);
            ldsm4(b1[0], b1[1], b1[2], b1[3], bOff1 + ks * 32);
#pragma unroll
            for (int rh = 0; rh < 2; rh++) {
                const uint32_t* Ah = rh ? ah1 : ah0;
                const uint32_t* Al = rh ? al1 : al0;
                mma16816(dst[rh * 4 + 0], Ah, b0[0], b0[1]);
                mma16816(dst[rh * 4 + 0], Al, b0[0], b0[1]);
                mma16816(dst[rh * 4 + 1], Ah, b0[2], b0[3]);
                mma16816(dst[rh * 4 + 1], Al, b0[2], b0[3]);
                mma16816(dst[rh * 4 + 2], Ah, b1[0], b1[1]);
                mma16816(dst[rh * 4 + 2], Al, b1[0], b1[1]);
                mma16816(dst[rh * 4 + 3], Ah, b1[2], b1[3]);
                mma16816(dst[rh * 4 + 3], Al, b1[2], b1[3]);
            }
        }
    };

    // ---- phase A: A_s + Wk -> K fragments (directly into kacc) ----
    stage_ln(true);
    stage_B(g_wk_h + (size_t)r * OUT_DIM * CAT_DIM, CAT_DIM / 8);
    __syncthreads();
    run2(kacc, CAT_DIM / 16);

    // ---- phase B: Wv -> V -> g_v ----
    __syncthreads();
    stage_B(g_wv_h + (size_t)r * OUT_DIM * CAT_DIM, CAT_DIM / 8);
    __syncthreads();
    run2(acc, CAT_DIM / 16);
    {
#pragma unroll
        for (int rh = 0; rh < 2; rh++) {
            int r0 = sr + rh * 16 + (lane >> 2);
            bool vA = r0 < ne, vB = (r0 + 8) < ne;
            size_t gA = vA ? (size_t)so[r0] * OUT_DIM : 0;
            size_t gB = vB ? (size_t)so[r0 + 8] * OUT_DIM : 0;
#pragma unroll
            for (int co = 0; co < 4; co++) {
                int c = cg + co * 8 + (lane & 3) * 2;
                int j = rh * 4 + co;
                if (vA) *(float2*)&g_v[gA + c] = make_float2(acc[j][0], acc[j][1]);
                if (vB) *(float2*)&g_v[gB + c] = make_float2(acc[j][2], acc[j][3]);
            }
        }
    }

    // ---- phase C: A_d + Wq -> Q fragments ----
    __syncthreads();
    stage_ln(false);
    stage_B(g_wq_h + (size_t)r * OUT_DIM * IN_DIM, IN_DIM / 8);
    __syncthreads();
    run2(acc, IN_DIM / 16);

    // ---- logits from fragments: a[e][h] = (q.k)/sqrt(128) ----
    {
#pragma unroll
        for (int rh = 0; rh < 2; rh++) {
            int r0 = sr + rh * 16 + (lane >> 2);
            bool vA = r0 < ne, vB = (r0 + 8) < ne;
#pragma unroll
            for (int hl = 0; hl < 2; hl++) {
                float sA = 0.f, sB = 0.f;
#pragma unroll
                for (int cc = 0; cc < 2; cc++) {
                    int j = rh * 4 + 2 * hl + cc;
                    sA += acc[j][0] * kacc[j][0] + acc[j][1] * kacc[j][1];
                    sB += acc[j][2] * kacc[j][2] + acc[j][3] * kacc[j][3];
                }
                sA += __shfl_xor_sync(0xffffffffu, sA, 1);
                sA += __shfl_xor_sync(0xffffffffu, sA, 2);
                sB += __shfl_xor_sync(0xffffffffu, sB, 1);
                sB += __shfl_xor_sync(0xffffffffu, sB, 2);
                if ((lane & 3) == 0) {
                    int h = (wid & 3) * 2 + hl;
                    if (vA) g_a[(size_t)so[r0] * H_HEADS + h] =
                                sA * 0.08838834764831845f;
                    if (vB) g_a[(size_t)so[r0 + 8] * H_HEADS + h] =
                                sB * 0.08838834764831845f;
                }
            }
        }
    }
}

// ---------------- fused softmax + weighted V (warp per node) ----------
__global__ void k_attn2(int M)
{
    int warp = (blockIdx.x * blockDim.x + threadIdx.x) >> 5;
    int lane = threadIdx.x & 31;
    if (warp >= M) return;
    const int m = warp;
    const int beg = g_doff[m];
    const int cnt = g_dhist[m];
    const int h = lane >> 2;

    float amax = -1e30f, denom = 0.f;
    for (int i = 0; i < cnt; i++) {
        int e = g_dorder[beg + i];
        float a = g_a[(size_t)e * H_HEADS + h];
        float nmax = fmaxf(amax, a);
        denom = denom * __expf(amax - nmax) + __expf(a - nmax);
        amax = nmax;
    }
    float inv = (cnt > 0) ? 1.f / denom : 0.f;

    const int c0 = lane * 4;
    float4 acc = make_float4(0.f, 0.f, 0.f, 0.f);
    for (int i = 0; i < cnt; i++) {
        int e = g_dorder[beg + i];
        float a = g_a[(size_t)e * H_HEADS + h];
        float alpha = __expf(a - amax) * inv;
        float4 v = *(const float4*)&g_v[(size_t)e * OUT_DIM + c0];
        acc.x += v.x * alpha;
        acc.y += v.y * alpha;
        acc.z += v.z * alpha;
        acc.w += v.w * alpha;
    }
    *(float4*)&g_hacc[(size_t)m * OUT_DIM + c0] = acc;
}

// ---------------- typed output projection (tiled by ntype) -------------
__global__ void __launch_bounds__(256, 2)
k_out_t(const float* __restrict__ Wa,
        const float* __restrict__ h_bias,
        const float* __restrict__ skip,
        const float* __restrict__ src_h,
        float* __restrict__ out, int M)
{
    const int r = blockIdx.y;
    const int cnt = g_ncur[r];
    const int tbase = blockIdx.x * TILE_M;
    if (tbase >= cnt) return;
    const size_t base = (size_t)r * M_MAX + tbase;
    const int ne = min(TILE_M, cnt - tbase);

    extern __shared__ float smf[];
    float* Ws = smf;
    float* Ds = smf + OUT_DIM * OUT_DIM;
    const int DS = TILE_M + 4;
    __shared__ int no[TILE_M];

    const int tid = threadIdx.x;
    if (tid < TILE_M) no[tid] = (tid < ne) ? g_norder[base + tid] : 0;
    __syncthreads();

    {
        const float* W = Wa + (size_t)r * OUT_DIM * OUT_DIM;
        for (int idx = tid; idx < OUT_DIM * (OUT_DIM / 4); idx += 256)
            ((float4*)Ws)[idx] = ((const float4*)W)[idx];
    }
    for (int idx = tid; idx < TILE_M * OUT_DIM; idx += 256) {
        int m = idx >> 7;
        int i = idx & 127;
        Ds[i * DS + m] = (m < ne) ?
            g_hacc[(size_t)no[m] * OUT_DIM + i] + h_bias[(size_t)r * OUT_DIM + i] : 0.f;
    }
    __syncthreads();

    const int c0 = (tid & 31) * 4;
    const int m0 = (tid >> 5) * 8;
    ull acc[4][4];
#pragma unroll
    for (int p = 0; p < 4; p++)
#pragma unroll
        for (int b = 0; b < 4; b++) acc[p][b] = 0ull;

#pragma unroll 8
    for (int i = 0; i < OUT_DIM; i++) {
        float4 w = *(const float4*)&Ws[i * OUT_DIM + c0];
        ull wd0 = dup2(w.x), wd1 = dup2(w.y), wd2 = dup2(w.z), wd3 = dup2(w.w);
        ulonglong2 p0 = *(const ulonglong2*)&Ds[i * DS + m0];
        ulonglong2 p1 = *(const ulonglong2*)&Ds[i * DS + m0 + 4];
        ull de[4] = {p0.x, p0.y, p1.x, p1.y};
#pragma unroll
        for (int p = 0; p < 4; p++) {
            acc[p][0] = fma2(de[p], wd0, acc[p][0]);
            acc[p][1] = fma2(de[p], wd1, acc[p][1]);
            acc[p][2] = fma2(de[p], wd2, acc[p][2]);
            acc[p][3] = fma2(de[p], wd3, acc[p][3]);
        }
    }

    float gate = 1.f / (1.f + __expf(-skip[r]));
    float og = 1.f - gate;
#pragma unroll
    for (int p = 0; p < 4; p++) {
        float2 v0 = unpk(acc[p][0]);
        float2 v1 = unpk(acc[p][1]);
        float2 v2 = unpk(acc[p][2]);
        float2 v3 = unpk(acc[p][3]);
        int mA = m0 + 2 * p, mB = mA + 1;
        if (mA < ne) {
            size_t gm = (size_t)no[mA] * OUT_DIM + c0;
            float4 s = *(const float4*)&src_h[gm];
            *(float4*)&out[gm] = make_float4(v0.x * gate + s.x * og,
                                             v1.x * gate + s.y * og,
                                             v2.x * gate + s.z * og,
                                             v3.x * gate + s.w * og);
        }
        if (mB < ne) {
            size_t gm = (size_t)no[mB] * OUT_DIM + c0;
            float4 s = *(const float4*)&src_h[gm];
            *(float4*)&out[gm] = make_float4(v0.y * gate + s.x * og,
                                             v1.y * gate + s.y * og,
                                             v2.y * gate + s.z * og,
                                             v3.y * gate + s.w * og);
        }
    }
}

// ---------------- launch ----------------
extern "C" void kernel_launch(void* const* d_in, const int* in_sizes, int n_in,
                              void* d_out, int out_size)
{
    const float* src_h  = (const float*)d_in[0];
    const float* src_tw = (const float*)d_in[1];
    const float* src_tb = (const float*)d_in[2];
    const float* edge_h = (const float*)d_in[3];
    const float* date   = (const float*)d_in[4];
    const int*   src_idx = (const int*)d_in[5];
    const int*   dst_idx = (const int*)d_in[6];
    const int*   etype   = (const int*)d_in[7];
    const int*   ntype   = (const int*)d_in[8];
    const float* Wq = (const float*)d_in[9];
    const float* Wk = (const float*)d_in[10];
    const float* Wv = (const float*)d_in[11];
    const float* Wa = (const float*)d_in[12];
    const float* h_bias = (const float*)d_in[13];
    const float* skip   = (const float*)d_in[14];
    const float* sg = (const float*)d_in[15];
    const float* sb = (const float*)d_in[16];
    const float* dg = (const float*)d_in[17];
    const float* db = (const float*)d_in[18];
    float* out = (float*)d_out;

    const int E = in_sizes[4];
    const int M = in_sizes[8];

    const int SMF = 3 * 128 * SA * 2;  // 129024
    const int SMO = (OUT_DIM * OUT_DIM + OUT_DIM * (TILE_M + 4)) * 4;
    cudaFuncSetAttribute(k_qkv, cudaFuncAttributeMaxDynamicSharedMemorySize, SMF);
    cudaFuncSetAttribute(k_out_t, cudaFuncAttributeMaxDynamicSharedMemorySize, SMO);

    int mx = (E > M) ? E : M;
    {
        dim3 gw((CAT_DIM / 32) * (OUT_DIM / 32), R_TYPES, 3);
        k_wconv2<<<gw, dim3(32, 8)>>>(Wq, Wk, Wv, M);
    }
    k_scatter_all<<<(mx + 255) / 256, 256>>>(etype, ntype, dst_idx, E, M);
    k_scan_dst<<<1, 1024>>>(M);
    k_scatter_dst<<<(E + 255) / 256, 256>>>(dst_idx, E);
    dim3 gq((E + TILE_E - 1) / TILE_E, R_TYPES);
    k_qkv<<<gq, 512, SMF>>>(src_h, src_tw, src_tb, edge_h, date,
                            src_idx, dst_idx, sg, sb, dg, db);
    k_attn2<<<(M * 32 + 255) / 256, 256>>>(M);
    dim3 go((M + TILE_M - 1) / TILE_M, T_TYPES);
    k_out_t<<<go, 256, SMO>>>(Wa, h_bias, skip, src_h, out, M);
}

// round 16
// speedup vs baseline: 2.0308x; 1.1295x over previous
#include <cuda_runtime.h>
#include <cuda_fp16.h>
#include <math.h>
#include <stdint.h>

// ---------------- problem constants ----------------
#define IN_DIM   128
#define E_DIM    32
#define CAT_DIM  160
#define OUT_DIM  128
#define TD       32
#define H_HEADS  8
#define HS       16
#define R_TYPES  8
#define T_TYPES  4
#define LN_EPS   1e-5f
#define E_MAX    100000
#define M_MAX    10000
#define TILE_E   128
#define TILE_M   64

typedef unsigned long long ull;

// ---------------- device scratch ----------------
// weights + LN activations: single fp16 plane (combined err ~3e-4 < 1e-3)
__device__ __half g_wq_h[(size_t)R_TYPES * OUT_DIM * IN_DIM];
__device__ __half g_wk_h[(size_t)R_TYPES * OUT_DIM * CAT_DIM];
__device__ __half g_wv_h[(size_t)R_TYPES * OUT_DIM * CAT_DIM];

__device__ float    g_v[(size_t)E_MAX * OUT_DIM];
__device__ float    g_a[(size_t)E_MAX * H_HEADS];
__device__ float    g_hacc[(size_t)M_MAX * OUT_DIM];

__device__ int      g_cur[R_TYPES];
__device__ int      g_order[(size_t)R_TYPES * E_MAX];
__device__ int      g_ncur[T_TYPES];
__device__ int      g_norder[(size_t)T_TYPES * M_MAX];
__device__ int      g_dhist[M_MAX], g_doff[M_MAX], g_dcur[M_MAX];
__device__ int      g_dorder[E_MAX];

// ---------------- f32x2 packed-FMA helpers (k_out) ----------------
__device__ __forceinline__ ull fma2(ull a, ull b, ull c) {
    ull d;
    asm("fma.rn.f32x2 %0, %1, %2, %3;" : "=l"(d) : "l"(a), "l"(b), "l"(c));
    return d;
}
__device__ __forceinline__ ull dup2(float x) {
    ull d; asm("mov.b64 %0, {%1, %1};" : "=l"(d) : "f"(x)); return d;
}
__device__ __forceinline__ float2 unpk(ull v) {
    float2 f; asm("mov.b64 {%0, %1}, %2;" : "=f"(f.x), "=f"(f.y) : "l"(v)); return f;
}

// ---------------- mma.sync helpers ----------------
__device__ __forceinline__ uint32_t smem_u32(const void* p) {
    uint32_t a;
    asm("{ .reg .u64 t; cvta.to.shared.u64 t, %1; cvt.u32.u64 %0, t; }"
        : "=r"(a) : "l"(p));
    return a;
}
__device__ __forceinline__ void ldsm4(uint32_t& r0, uint32_t& r1, uint32_t& r2,
                                      uint32_t& r3, uint32_t addr) {
    asm volatile("ldmatrix.sync.aligned.m8n8.x4.shared.b16 {%0,%1,%2,%3}, [%4];"
                 : "=r"(r0), "=r"(r1), "=r"(r2), "=r"(r3) : "r"(addr));
}
__device__ __forceinline__ void mma16816(float* d, const uint32_t* a,
                                         uint32_t b0, uint32_t b1) {
    asm volatile(
        "mma.sync.aligned.m16n8k16.row.col.f32.f16.f16.f32 "
        "{%0,%1,%2,%3}, {%4,%5,%6,%7}, {%8,%9}, {%0,%1,%2,%3};"
        : "+f"(d[0]), "+f"(d[1]), "+f"(d[2]), "+f"(d[3])
        : "r"(a[0]), "r"(a[1]), "r"(a[2]), "r"(a[3]), "r"(b0), "r"(b1));
}

// ---------------- scatter: etype buckets, ntype buckets, dst histogram ----
__global__ void k_scatter_all(const int* __restrict__ etype,
                              const int* __restrict__ ntype,
                              const int* __restrict__ dst_idx,
                              int E, int M) {
    int t = blockIdx.x * blockDim.x + threadIdx.x;
    int lane = threadIdx.x & 31;
    unsigned actE = __ballot_sync(0xffffffffu, t < E);
    if (t < E) {
        int r = etype[t];
        unsigned m = __match_any_sync(actE, r);
        int leader = __ffs(m) - 1;
        int rank = __popc(m & ((1u << lane) - 1));
        int base = 0;
        if (lane == leader) base = atomicAdd(&g_cur[r], __popc(m));
        base = __shfl_sync(actE, base, leader);
        g_order[(size_t)r * E_MAX + base + rank] = t;
        atomicAdd(&g_dhist[dst_idx[t]], 1);
    }
    unsigned actM = __ballot_sync(0xffffffffu, t < M);
    if (t < M) {
        int r = ntype[t];
        unsigned m = __match_any_sync(actM, r);
        int leader = __ffs(m) - 1;
        int rank = __popc(m & ((1u << lane) - 1));
        int base = 0;
        if (lane == leader) base = atomicAdd(&g_ncur[r], __popc(m));
        base = __shfl_sync(actM, base, leader);
        g_norder[(size_t)r * M_MAX + base + rank] = t;
    }
}

// ---------------- single-block exclusive scan of g_dhist -> g_doff -------
__global__ void __launch_bounds__(1024, 1) k_scan_dst(int M) {
    const int tid = threadIdx.x;
    const int per = (M + 1023) / 1024;
    const int start = tid * per;
    const int end = min(start + per, M);
    int local = 0;
    for (int i = start; i < end; i++) local += g_dhist[i];
    __shared__ int wsum[32];
    int lane = tid & 31, w = tid >> 5;
    int v = local;
#pragma unroll
    for (int o = 1; o < 32; o <<= 1) {
        int u = __shfl_up_sync(0xffffffffu, v, o);
        if (lane >= o) v += u;
    }
    if (lane == 31) wsum[w] = v;
    __syncthreads();
    if (w == 0) {
        int s = wsum[lane];
#pragma unroll
        for (int o = 1; o < 32; o <<= 1) {
            int u = __shfl_up_sync(0xffffffffu, s, o);
            if (lane >= o) s += u;
        }
        wsum[lane] = s;
    }
    __syncthreads();
    int run = v - local + (w > 0 ? wsum[w - 1] : 0);
    for (int i = start; i < end; i++) { g_doff[i] = run; run += g_dhist[i]; }
}

__global__ void k_scatter_dst(const int* __restrict__ dst_idx, int E) {
    int e = blockIdx.x * blockDim.x + threadIdx.x;
    if (e < E) {
        int d = dst_idx[e];
        int p = atomicAdd(&g_dcur[d], 1);
        g_dorder[g_doff[d] + p] = e;
    }
}

// ---------------- weight transpose + fp16 convert (+ fused reset) --------
__global__ void k_wconv2(const float* __restrict__ Wq,
                         const float* __restrict__ Wk,
                         const float* __restrict__ Wv, int M) {
    const int which = blockIdx.z;      // 0=Q, 1=K, 2=V
    const int r = blockIdx.y;
    const int KD = (which == 0) ? IN_DIM : CAT_DIM;
    const int ntiles_n = OUT_DIM / 32;
    const int tile = blockIdx.x;
    const int kt = tile / ntiles_n;
    const int nt = tile - kt * ntiles_n;
    if (kt * 32 >= KD) {
        if (which == 0 && r == 0) {
            int t = (tile - 16) * 256 + threadIdx.y * 32 + threadIdx.x;
            for (int i = t; i < M; i += 4 * 256) { g_dhist[i] = 0; g_dcur[i] = 0; }
            if (t < R_TYPES) g_cur[t] = 0;
            if (t < T_TYPES) g_ncur[t] = 0;
        }
        return;
    }

    const float* W = (which == 0 ? Wq : which == 1 ? Wk : Wv)
                   + (size_t)r * KD * OUT_DIM;
    __half* wh = (which == 0 ? g_wq_h : which == 1 ? g_wk_h : g_wv_h)
               + (size_t)r * OUT_DIM * KD;

    __shared__ float smt[32][33];
    const int tx = threadIdx.x, ty = threadIdx.y;  // 32 x 8
#pragma unroll
    for (int dy = 0; dy < 4; dy++) {
        int k = kt * 32 + ty + dy * 8;
        smt[ty + dy * 8][tx] = W[(size_t)k * OUT_DIM + nt * 32 + tx];
    }
    __syncthreads();
#pragma unroll
    for (int dy = 0; dy < 4; dy++) {
        int n = nt * 32 + ty + dy * 8;
        int k = kt * 32 + tx;
        wh[(size_t)n * KD + k] = __float2half_rn(smt[tx][ty + dy * 8]);
    }
}

// ---------------- fully fused QKV + logits kernel (32x32 warp tiles) ------
// A = LN output fp16, B = fp16 weights, single pass.
#define SA  (CAT_DIM + 8)     // unified row stride (fp16 elems) = 168
#define SAB (SA * 2)          // 336 bytes

__global__ void __launch_bounds__(512, 1)
k_qkv(const float* __restrict__ src_h,
      const float* __restrict__ src_tw,
      const float* __restrict__ src_tb,
      const float* __restrict__ edge_h,
      const float* __restrict__ date,
      const int*   __restrict__ src_idx,
      const int*   __restrict__ dst_idx,
      const float* __restrict__ sg, const float* __restrict__ sb,
      const float* __restrict__ dg, const float* __restrict__ db)
{
    const int r = blockIdx.y;
    const int cnt = g_cur[r];
    const int tb = blockIdx.x * TILE_E;
    if (tb >= cnt) return;
    const size_t base = (size_t)r * E_MAX + tb;
    const int ne = min(TILE_E, cnt - tb);

    extern __shared__ __align__(16) char sm[];
    __half* aF = (__half*)sm;
    __half* bF = aF + 128 * SA;
    __shared__ int so[TILE_E];

    const int tid = threadIdx.x, wid = tid >> 5, lane = tid & 31;
    if (tid < TILE_E) so[tid] = (tid < ne) ? g_order[base + tid] : 0;
    __syncthreads();

    // ---------- fused LN staging: 2 batches of 4 rows per warp ----------
    auto stage_ln = [&](bool SRC) {
        const int NR = SRC ? 5 : 4;
        const float inv_kd = SRC ? (1.0f / CAT_DIM) : (1.0f / IN_DIM);
        const float* lng = SRC ? sg : dg;
        const float* lnb = SRC ? sb : db;
#pragma unroll
        for (int half = 0; half < 2; half++) {
            int eA[4]; int ndA[4]; float tA[4];
#pragma unroll
            for (int b4 = 0; b4 < 4; b4++) {
                int i = wid * 8 + half * 4 + b4;
                int e = so[i < ne ? i : 0];
                eA[b4] = e;
                ndA[b4] = SRC ? src_idx[e] : dst_idx[e];
                tA[b4] = date[e];
            }
            float xs[4][5];
#pragma unroll
            for (int b4 = 0; b4 < 4; b4++) {
                int nd = ndA[b4];
                xs[b4][0] = __sinf(src_tw[(size_t)nd * TD + lane] * tA[b4] +
                                   src_tb[(size_t)nd * TD + lane]) *
                            src_h[(size_t)nd * IN_DIM + lane];
#pragma unroll
                for (int k = 1; k < 4; k++)
                    xs[b4][k] = src_h[(size_t)nd * IN_DIM + lane + 32 * k];
                if (SRC) xs[b4][4] = edge_h[(size_t)eA[b4] * E_DIM + lane];
            }
            float mu[4], rstd[4];
#pragma unroll
            for (int b4 = 0; b4 < 4; b4++) {
                float s = 0.f;
                for (int k = 0; k < NR; k++) s += xs[b4][k];
#pragma unroll
                for (int o = 16; o > 0; o >>= 1) s += __shfl_xor_sync(0xffffffffu, s, o);
                mu[b4] = s * inv_kd;
            }
#pragma unroll
            for (int b4 = 0; b4 < 4; b4++) {
                float s = 0.f;
                for (int k = 0; k < NR; k++) { float d = xs[b4][k] - mu[b4]; s += d * d; }
#pragma unroll
                for (int o = 16; o > 0; o >>= 1) s += __shfl_xor_sync(0xffffffffu, s, o);
                rstd[b4] = rsqrtf(s * inv_kd + LN_EPS);
            }
#pragma unroll
            for (int b4 = 0; b4 < 4; b4++) {
                int i = wid * 8 + half * 4 + b4;
                __half* row = aF + i * SA;
                bool valid = i < ne;
                for (int k = 0; k < NR; k++) {
                    int j = lane + 32 * k;
                    float y = valid ? (xs[b4][k] - mu[b4]) * rstd[b4] * lng[j] + lnb[j] : 0.f;
                    row[j] = __float2half_rn(y);
                }
            }
        }
    };

    auto stage_B = [&](const __half* wh, int U) {
        for (int idx = tid; idx < 128 * U; idx += 512) {
            int n = idx / U, u = idx - n * U;
            *(uint4*)((char*)bF + n * SAB + u * 16) = ((const uint4*)(wh + (size_t)n * (U * 8)))[u];
        }
    };

    // 32x32 warp tile: 4 row-stripes x 4 col-groups
    const int sr = (wid >> 2) * 32;
    const int cg = (wid & 3) * 32;

    const uint32_t aOff0 = smem_u32(aF) + (uint32_t)(sr + (lane & 15)) * SAB
                         + (uint32_t)(lane >> 4) * 16;
    const uint32_t aOff1 = aOff0 + (uint32_t)(16 * SAB);
    const int brow = ((lane >> 4) & 1) * 8 + (lane & 7);
    const int bko  = ((lane >> 3) & 1) * 16;
    const uint32_t bOff0 = smem_u32(bF) + (uint32_t)(cg + brow) * SAB + bko;
    const uint32_t bOff1 = bOff0 + (uint32_t)(16 * SAB);

    float acc[8][4], kacc[8][4];   // [rh*4 + co][4]

    // single-pass product: 4 LDSM + 8 HMMA per k-chunk
    auto run1 = [&](float (*dst)[4], int nk) {
#pragma unroll
        for (int j = 0; j < 8; j++)
#pragma unroll
            for (int b = 0; b < 4; b++) dst[j][b] = 0.f;
#pragma unroll
        for (int ks = 0; ks < 10; ks++) {
            if (ks >= nk) break;
            uint32_t a0[4], a1[4];
            ldsm4(a0[0], a0[1], a0[2], a0[3], aOff0 + ks * 32);
            ldsm4(a1[0], a1[1], a1[2], a1[3], aOff1 + ks * 32);
            uint32_t b0[4], b1[4];
            ldsm4(b0[0], b0[1], b0[2], b0[3], bOff0 + ks * 32);
            ldsm4(b1[0], b1[1], b1[2], b1[3], bOff1 + ks * 32);
#pragma unroll
            for (int rh = 0; rh < 2; rh++) {
                const uint32_t* A = rh ? a1 : a0;
                mma16816(dst[rh * 4 + 0], A, b0[0], b0[1]);
                mma16816(dst[rh * 4 + 1], A, b0[2], b0[3]);
                mma16816(dst[rh * 4 + 2], A, b1[0], b1[1]);
                mma16816(dst[rh * 4 + 3], A, b1[2], b1[3]);
            }
        }
    };

    // ---- phase A: A_s + Wk -> K fragments (directly into kacc) ----
    stage_ln(true);
    stage_B(g_wk_h + (size_t)r * OUT_DIM * CAT_DIM, CAT_DIM / 8);
    __syncthreads();
    run1(kacc, CAT_DIM / 16);

    // ---- phase B: Wv -> V -> g_v ----
    __syncthreads();
    stage_B(g_wv_h + (size_t)r * OUT_DIM * CAT_DIM, CAT_DIM / 8);
    __syncthreads();
    run1(acc, CAT_DIM / 16);
    {
#pragma unroll
        for (int rh = 0; rh < 2; rh++) {
            int r0 = sr + rh * 16 + (lane >> 2);
            bool vA = r0 < ne, vB = (r0 + 8) < ne;
            size_t gA = vA ? (size_t)so[r0] * OUT_DIM : 0;
            size_t gB = vB ? (size_t)so[r0 + 8] * OUT_DIM : 0;
#pragma unroll
            for (int co = 0; co < 4; co++) {
                int c = cg + co * 8 + (lane & 3) * 2;
                int j = rh * 4 + co;
                if (vA) *(float2*)&g_v[gA + c] = make_float2(acc[j][0], acc[j][1]);
                if (vB) *(float2*)&g_v[gB + c] = make_float2(acc[j][2], acc[j][3]);
            }
        }
    }

    // ---- phase C: A_d + Wq -> Q fragments ----
    __syncthreads();
    stage_ln(false);
    stage_B(g_wq_h + (size_t)r * OUT_DIM * IN_DIM, IN_DIM / 8);
    __syncthreads();
    run1(acc, IN_DIM / 16);

    // ---- logits from fragments: a[e][h] = (q.k)/sqrt(128) ----
    {
#pragma unroll
        for (int rh = 0; rh < 2; rh++) {
            int r0 = sr + rh * 16 + (lane >> 2);
            bool vA = r0 < ne, vB = (r0 + 8) < ne;
#pragma unroll
            for (int hl = 0; hl < 2; hl++) {
                float sA = 0.f, sB = 0.f;
#pragma unroll
                for (int cc = 0; cc < 2; cc++) {
                    int j = rh * 4 + 2 * hl + cc;
                    sA += acc[j][0] * kacc[j][0] + acc[j][1] * kacc[j][1];
                    sB += acc[j][2] * kacc[j][2] + acc[j][3] * kacc[j][3];
                }
                sA += __shfl_xor_sync(0xffffffffu, sA, 1);
                sA += __shfl_xor_sync(0xffffffffu, sA, 2);
                sB += __shfl_xor_sync(0xffffffffu, sB, 1);
                sB += __shfl_xor_sync(0xffffffffu, sB, 2);
                if ((lane & 3) == 0) {
                    int h = (wid & 3) * 2 + hl;
                    if (vA) g_a[(size_t)so[r0] * H_HEADS + h] =
                                sA * 0.08838834764831845f;
                    if (vB) g_a[(size_t)so[r0 + 8] * H_HEADS + h] =
                                sB * 0.08838834764831845f;
                }
            }
        }
    }
}

// ---------------- fused softmax + weighted V (warp per node) ----------
__global__ void k_attn2(int M)
{
    int warp = (blockIdx.x * blockDim.x + threadIdx.x) >> 5;
    int lane = threadIdx.x & 31;
    if (warp >= M) return;
    const int m = warp;
    const int beg = g_doff[m];
    const int cnt = g_dhist[m];
    const int h = lane >> 2;

    float amax = -1e30f, denom = 0.f;
    for (int i = 0; i < cnt; i++) {
        int e = g_dorder[beg + i];
        float a = g_a[(size_t)e * H_HEADS + h];
        float nmax = fmaxf(amax, a);
        denom = denom * __expf(amax - nmax) + __expf(a - nmax);
        amax = nmax;
    }
    float inv = (cnt > 0) ? 1.f / denom : 0.f;

    const int c0 = lane * 4;
    float4 acc = make_float4(0.f, 0.f, 0.f, 0.f);
    for (int i = 0; i < cnt; i++) {
        int e = g_dorder[beg + i];
        float a = g_a[(size_t)e * H_HEADS + h];
        float alpha = __expf(a - amax) * inv;
        float4 v = *(const float4*)&g_v[(size_t)e * OUT_DIM + c0];
        acc.x += v.x * alpha;
        acc.y += v.y * alpha;
        acc.z += v.z * alpha;
        acc.w += v.w * alpha;
    }
    *(float4*)&g_hacc[(size_t)m * OUT_DIM + c0] = acc;
}

// ---------------- typed output projection (tiled by ntype) -------------
__global__ void __launch_bounds__(256, 2)
k_out_t(const float* __restrict__ Wa,
        const float* __restrict__ h_bias,
        const float* __restrict__ skip,
        const float* __restrict__ src_h,
        float* __restrict__ out, int M)
{
    const int r = blockIdx.y;
    const int cnt = g_ncur[r];
    const int tbase = blockIdx.x * TILE_M;
    if (tbase >= cnt) return;
    const size_t base = (size_t)r * M_MAX + tbase;
    const int ne = min(TILE_M, cnt - tbase);

    extern __shared__ float smf[];
    float* Ws = smf;
    float* Ds = smf + OUT_DIM * OUT_DIM;
    const int DS = TILE_M + 4;
    __shared__ int no[TILE_M];

    const int tid = threadIdx.x;
    if (tid < TILE_M) no[tid] = (tid < ne) ? g_norder[base + tid] : 0;
    __syncthreads();

    {
        const float* W = Wa + (size_t)r * OUT_DIM * OUT_DIM;
        for (int idx = tid; idx < OUT_DIM * (OUT_DIM / 4); idx += 256)
            ((float4*)Ws)[idx] = ((const float4*)W)[idx];
    }
    for (int idx = tid; idx < TILE_M * OUT_DIM; idx += 256) {
        int m = idx >> 7;
        int i = idx & 127;
        Ds[i * DS + m] = (m < ne) ?
            g_hacc[(size_t)no[m] * OUT_DIM + i] + h_bias[(size_t)r * OUT_DIM + i] : 0.f;
    }
    __syncthreads();

    const int c0 = (tid & 31) * 4;
    const int m0 = (tid >> 5) * 8;
    ull acc[4][4];
#pragma unroll
    for (int p = 0; p < 4; p++)
#pragma unroll
        for (int b = 0; b < 4; b++) acc[p][b] = 0ull;

#pragma unroll 8
    for (int i = 0; i < OUT_DIM; i++) {
        float4 w = *(const float4*)&Ws[i * OUT_DIM + c0];
        ull wd0 = dup2(w.x), wd1 = dup2(w.y), wd2 = dup2(w.z), wd3 = dup2(w.w);
        ulonglong2 p0 = *(const ulonglong2*)&Ds[i * DS + m0];
        ulonglong2 p1 = *(const ulonglong2*)&Ds[i * DS + m0 + 4];
        ull de[4] = {p0.x, p0.y, p1.x, p1.y};
#pragma unroll
        for (int p = 0; p < 4; p++) {
            acc[p][0] = fma2(de[p], wd0, acc[p][0]);
            acc[p][1] = fma2(de[p], wd1, acc[p][1]);
            acc[p][2] = fma2(de[p], wd2, acc[p][2]);
            acc[p][3] = fma2(de[p], wd3, acc[p][3]);
        }
    }

    float gate = 1.f / (1.f + __expf(-skip[r]));
    float og = 1.f - gate;
#pragma unroll
    for (int p = 0; p < 4; p++) {
        float2 v0 = unpk(acc[p][0]);
        float2 v1 = unpk(acc[p][1]);
        float2 v2 = unpk(acc[p][2]);
        float2 v3 = unpk(acc[p][3]);
        int mA = m0 + 2 * p, mB = mA + 1;
        if (mA < ne) {
            size_t gm = (size_t)no[mA] * OUT_DIM + c0;
            float4 s = *(const float4*)&src_h[gm];
            *(float4*)&out[gm] = make_float4(v0.x * gate + s.x * og,
                                             v1.x * gate + s.y * og,
                                             v2.x * gate + s.z * og,
                                             v3.x * gate + s.w * og);
        }
        if (mB < ne) {
            size_t gm = (size_t)no[mB] * OUT_DIM + c0;
            float4 s = *(const float4*)&src_h[gm];
            *(float4*)&out[gm] = make_float4(v0.y * gate + s.x * og,
                                             v1.y * gate + s.y * og,
                                             v2.y * gate + s.z * og,
                                             v3.y * gate + s.w * og);
        }
    }
}

// ---------------- launch ----------------
extern "C" void kernel_launch(void* const* d_in, const int* in_sizes, int n_in,
                              void* d_out, int out_size)
{
    const float* src_h  = (const float*)d_in[0];
    const float* src_tw = (const float*)d_in[1];
    const float* src_tb = (const float*)d_in[2];
    const float* edge_h = (const float*)d_in[3];
    const float* date   = (const float*)d_in[4];
    const int*   src_idx = (const int*)d_in[5];
    const int*   dst_idx = (const int*)d_in[6];
    const int*   etype   = (const int*)d_in[7];
    const int*   ntype   = (const int*)d_in[8];
    const float* Wq = (const float*)d_in[9];
    const float* Wk = (const float*)d_in[10];
    const float* Wv = (const float*)d_in[11];
    const float* Wa = (const float*)d_in[12];
    const float* h_bias = (const float*)d_in[13];
    const float* skip   = (const float*)d_in[14];
    const float* sg = (const float*)d_in[15];
    const float* sb = (const float*)d_in[16];
    const float* dg = (const float*)d_in[17];
    const float* db = (const float*)d_in[18];
    float* out = (float*)d_out;

    const int E = in_sizes[4];
    const int M = in_sizes[8];

    const int SMF = 2 * 128 * SA * 2;  // 86016
    const int SMO = (OUT_DIM * OUT_DIM + OUT_DIM * (TILE_M + 4)) * 4;
    cudaFuncSetAttribute(k_qkv, cudaFuncAttributeMaxDynamicSharedMemorySize, SMF);
    cudaFuncSetAttribute(k_out_t, cudaFuncAttributeMaxDynamicSharedMemorySize, SMO);

    int mx = (E > M) ? E : M;
    {
        dim3 gw((CAT_DIM / 32) * (OUT_DIM / 32), R_TYPES, 3);
        k_wconv2<<<gw, dim3(32, 8)>>>(Wq, Wk, Wv, M);
    }
    k_scatter_all<<<(mx + 255) / 256, 256>>>(etype, ntype, dst_idx, E, M);
    k_scan_dst<<<1, 1024>>>(M);
    k_scatter_dst<<<(E + 255) / 256, 256>>>(dst_idx, E);
    dim3 gq((E + TILE_E - 1) / TILE_E, R_TYPES);
    k_qkv<<<gq, 512, SMF>>>(src_h, src_tw, src_tb, edge_h, date,
                            src_idx, dst_idx, sg, sb, dg, db);
    k_attn2<<<(M * 32 + 255) / 256, 256>>>(M);
    dim3 go((M + TILE_M - 1) / TILE_M, T_TYPES);
    k_out_t<<<go, 256, SMO>>>(Wa, h_bias, skip, src_h, out, M);
}

// round 17
// speedup vs baseline: 2.0371x; 1.0031x over previous
#include <cuda_runtime.h>
#include <cuda_fp16.h>
#include <math.h>
#include <stdint.h>

// ---------------- problem constants ----------------
#define IN_DIM   128
#define E_DIM    32
#define CAT_DIM  160
#define OUT_DIM  128
#define TD       32
#define H_HEADS  8
#define HS       16
#define R_TYPES  8
#define T_TYPES  4
#define LN_EPS   1e-5f
#define E_MAX    100000
#define M_MAX    10000
#define TILE_E   128
#define TILE_M   64

typedef unsigned long long ull;

// ---------------- device scratch ----------------
__device__ __half g_wq_h[(size_t)R_TYPES * OUT_DIM * IN_DIM];
__device__ __half g_wk_h[(size_t)R_TYPES * OUT_DIM * CAT_DIM];
__device__ __half g_wv_h[(size_t)R_TYPES * OUT_DIM * CAT_DIM];

__device__ float    g_v[(size_t)E_MAX * OUT_DIM];
__device__ float    g_a[(size_t)E_MAX * H_HEADS];
__device__ float    g_hacc[(size_t)M_MAX * OUT_DIM];

__device__ int      g_cur[R_TYPES];
__device__ int      g_order[(size_t)R_TYPES * E_MAX];
__device__ int      g_ncur[T_TYPES];
__device__ int      g_norder[(size_t)T_TYPES * M_MAX];
__device__ int      g_dhist[M_MAX], g_doff[M_MAX], g_dcur[M_MAX];
__device__ int      g_dorder[E_MAX];

// ---------------- f32x2 packed-FMA helpers (k_out) ----------------
__device__ __forceinline__ ull fma2(ull a, ull b, ull c) {
    ull d;
    asm("fma.rn.f32x2 %0, %1, %2, %3;" : "=l"(d) : "l"(a), "l"(b), "l"(c));
    return d;
}
__device__ __forceinline__ ull dup2(float x) {
    ull d; asm("mov.b64 %0, {%1, %1};" : "=l"(d) : "f"(x)); return d;
}
__device__ __forceinline__ float2 unpk(ull v) {
    float2 f; asm("mov.b64 {%0, %1}, %2;" : "=f"(f.x), "=f"(f.y) : "l"(v)); return f;
}

// ---------------- mma.sync helpers ----------------
__device__ __forceinline__ uint32_t smem_u32(const void* p) {
    uint32_t a;
    asm("{ .reg .u64 t; cvta.to.shared.u64 t, %1; cvt.u32.u64 %0, t; }"
        : "=r"(a) : "l"(p));
    return a;
}
__device__ __forceinline__ void ldsm4(uint32_t& r0, uint32_t& r1, uint32_t& r2,
                                      uint32_t& r3, uint32_t addr) {
    asm volatile("ldmatrix.sync.aligned.m8n8.x4.shared.b16 {%0,%1,%2,%3}, [%4];"
                 : "=r"(r0), "=r"(r1), "=r"(r2), "=r"(r3) : "r"(addr));
}
__device__ __forceinline__ void mma16816(float* d, const uint32_t* a,
                                         uint32_t b0, uint32_t b1) {
    asm volatile(
        "mma.sync.aligned.m16n8k16.row.col.f32.f16.f16.f32 "
        "{%0,%1,%2,%3}, {%4,%5,%6,%7}, {%8,%9}, {%0,%1,%2,%3};"
        : "+f"(d[0]), "+f"(d[1]), "+f"(d[2]), "+f"(d[3])
        : "r"(a[0]), "r"(a[1]), "r"(a[2]), "r"(a[3]), "r"(b0), "r"(b1));
}

// ---------------- scatter: etype buckets, ntype buckets, dst histogram ----
__global__ void k_scatter_all(const int* __restrict__ etype,
                              const int* __restrict__ ntype,
                              const int* __restrict__ dst_idx,
                              int E, int M) {
    int t = blockIdx.x * blockDim.x + threadIdx.x;
    int lane = threadIdx.x & 31;
    unsigned actE = __ballot_sync(0xffffffffu, t < E);
    if (t < E) {
        int r = etype[t];
        unsigned m = __match_any_sync(actE, r);
        int leader = __ffs(m) - 1;
        int rank = __popc(m & ((1u << lane) - 1));
        int base = 0;
        if (lane == leader) base = atomicAdd(&g_cur[r], __popc(m));
        base = __shfl_sync(actE, base, leader);
        g_order[(size_t)r * E_MAX + base + rank] = t;
        atomicAdd(&g_dhist[dst_idx[t]], 1);
    }
    unsigned actM = __ballot_sync(0xffffffffu, t < M);
    if (t < M) {
        int r = ntype[t];
        unsigned m = __match_any_sync(actM, r);
        int leader = __ffs(m) - 1;
        int rank = __popc(m & ((1u << lane) - 1));
        int base = 0;
        if (lane == leader) base = atomicAdd(&g_ncur[r], __popc(m));
        base = __shfl_sync(actM, base, leader);
        g_norder[(size_t)r * M_MAX + base + rank] = t;
    }
}

// ---------------- single-block exclusive scan of g_dhist -> g_doff -------
__global__ void __launch_bounds__(1024, 1) k_scan_dst(int M) {
    const int tid = threadIdx.x;
    const int per = (M + 1023) / 1024;
    const int start = tid * per;
    const int end = min(start + per, M);
    int local = 0;
    for (int i = start; i < end; i++) local += g_dhist[i];
    __shared__ int wsum[32];
    int lane = tid & 31, w = tid >> 5;
    int v = local;
#pragma unroll
    for (int o = 1; o < 32; o <<= 1) {
        int u = __shfl_up_sync(0xffffffffu, v, o);
        if (lane >= o) v += u;
    }
    if (lane == 31) wsum[w] = v;
    __syncthreads();
    if (w == 0) {
        int s = wsum[lane];
#pragma unroll
        for (int o = 1; o < 32; o <<= 1) {
            int u = __shfl_up_sync(0xffffffffu, s, o);
            if (lane >= o) s += u;
        }
        wsum[lane] = s;
    }
    __syncthreads();
    int run = v - local + (w > 0 ? wsum[w - 1] : 0);
    for (int i = start; i < end; i++) { g_doff[i] = run; run += g_dhist[i]; }
}

__global__ void k_scatter_dst(const int* __restrict__ dst_idx, int E) {
    int e = blockIdx.x * blockDim.x + threadIdx.x;
    if (e < E) {
        int d = dst_idx[e];
        int p = atomicAdd(&g_dcur[d], 1);
        g_dorder[g_doff[d] + p] = e;
    }
}

// ---------------- weight transpose + fp16 convert (+ fused reset) --------
__global__ void k_wconv2(const float* __restrict__ Wq,
                         const float* __restrict__ Wk,
                         const float* __restrict__ Wv, int M) {
    const int which = blockIdx.z;      // 0=Q, 1=K, 2=V
    const int r = blockIdx.y;
    const int KD = (which == 0) ? IN_DIM : CAT_DIM;
    const int ntiles_n = OUT_DIM / 32;
    const int tile = blockIdx.x;
    const int kt = tile / ntiles_n;
    const int nt = tile - kt * ntiles_n;
    if (kt * 32 >= KD) {
        if (which == 0 && r == 0) {
            int t = (tile - 16) * 256 + threadIdx.y * 32 + threadIdx.x;
            for (int i = t; i < M; i += 4 * 256) { g_dhist[i] = 0; g_dcur[i] = 0; }
            if (t < R_TYPES) g_cur[t] = 0;
            if (t < T_TYPES) g_ncur[t] = 0;
        }
        return;
    }

    const float* W = (which == 0 ? Wq : which == 1 ? Wk : Wv)
                   + (size_t)r * KD * OUT_DIM;
    __half* wh = (which == 0 ? g_wq_h : which == 1 ? g_wk_h : g_wv_h)
               + (size_t)r * OUT_DIM * KD;

    __shared__ float smt[32][33];
    const int tx = threadIdx.x, ty = threadIdx.y;  // 32 x 8
#pragma unroll
    for (int dy = 0; dy < 4; dy++) {
        int k = kt * 32 + ty + dy * 8;
        smt[ty + dy * 8][tx] = W[(size_t)k * OUT_DIM + nt * 32 + tx];
    }
    __syncthreads();
#pragma unroll
    for (int dy = 0; dy < 4; dy++) {
        int n = nt * 32 + ty + dy * 8;
        int k = kt * 32 + tx;
        wh[(size_t)n * KD + k] = __float2half_rn(smt[tx][ty + dy * 8]);
    }
}

// ---------------- fully fused QKV + logits kernel ----------------
// ALL staging up front (A_s, A_d, B_k, B_v, B_q in 215 KB smem), ONE barrier,
// then three back-to-back single-pass MMA bursts with no further syncs.
#define SA  (CAT_DIM + 8)     // unified row stride (fp16 elems) = 168
#define SAB (SA * 2)          // 336 bytes
#define REG (128 * SAB)       // one 128-row region = 43008 bytes

__global__ void __launch_bounds__(512, 1)
k_qkv(const float* __restrict__ src_h,
      const float* __restrict__ src_tw,
      const float* __restrict__ src_tb,
      const float* __restrict__ edge_h,
      const float* __restrict__ date,
      const int*   __restrict__ src_idx,
      const int*   __restrict__ dst_idx,
      const float* __restrict__ sg, const float* __restrict__ sb,
      const float* __restrict__ dg, const float* __restrict__ db)
{
    const int r = blockIdx.y;
    const int cnt = g_cur[r];
    const int tb = blockIdx.x * TILE_E;
    if (tb >= cnt) return;
    const size_t base = (size_t)r * E_MAX + tb;
    const int ne = min(TILE_E, cnt - tb);

    extern __shared__ __align__(16) char sm[];
    __half* aS = (__half*)sm;                 // region 0: src LN tile
    __half* aD = (__half*)(sm + REG);         // region 1: dst LN tile
    __half* bK = (__half*)(sm + 2 * REG);     // region 2: Wk
    __half* bV = (__half*)(sm + 3 * REG);     // region 3: Wv
    __half* bQ = (__half*)(sm + 4 * REG);     // region 4: Wq
    __shared__ int so[TILE_E];

    const int tid = threadIdx.x, wid = tid >> 5, lane = tid & 31;
    if (tid < TILE_E) so[tid] = (tid < ne) ? g_order[base + tid] : 0;
    __syncthreads();

    // ---------- fused LN staging: 2 batches of 4 rows per warp ----------
    auto stage_ln = [&](bool SRC, __half* dst) {
        const int NR = SRC ? 5 : 4;
        const float inv_kd = SRC ? (1.0f / CAT_DIM) : (1.0f / IN_DIM);
        const float* lng = SRC ? sg : dg;
        const float* lnb = SRC ? sb : db;
#pragma unroll
        for (int half = 0; half < 2; half++) {
            int eA[4]; int ndA[4]; float tA[4];
#pragma unroll
            for (int b4 = 0; b4 < 4; b4++) {
                int i = wid * 8 + half * 4 + b4;
                int e = so[i < ne ? i : 0];
                eA[b4] = e;
                ndA[b4] = SRC ? src_idx[e] : dst_idx[e];
                tA[b4] = date[e];
            }
            float xs[4][5];
#pragma unroll
            for (int b4 = 0; b4 < 4; b4++) {
                int nd = ndA[b4];
                xs[b4][0] = __sinf(src_tw[(size_t)nd * TD + lane] * tA[b4] +
                                   src_tb[(size_t)nd * TD + lane]) *
                            src_h[(size_t)nd * IN_DIM + lane];
#pragma unroll
                for (int k = 1; k < 4; k++)
                    xs[b4][k] = src_h[(size_t)nd * IN_DIM + lane + 32 * k];
                if (SRC) xs[b4][4] = edge_h[(size_t)eA[b4] * E_DIM + lane];
            }
            float mu[4], rstd[4];
#pragma unroll
            for (int b4 = 0; b4 < 4; b4++) {
                float s = 0.f;
                for (int k = 0; k < NR; k++) s += xs[b4][k];
#pragma unroll
                for (int o = 16; o > 0; o >>= 1) s += __shfl_xor_sync(0xffffffffu, s, o);
                mu[b4] = s * inv_kd;
            }
#pragma unroll
            for (int b4 = 0; b4 < 4; b4++) {
                float s = 0.f;
                for (int k = 0; k < NR; k++) { float d = xs[b4][k] - mu[b4]; s += d * d; }
#pragma unroll
                for (int o = 16; o > 0; o >>= 1) s += __shfl_xor_sync(0xffffffffu, s, o);
                rstd[b4] = rsqrtf(s * inv_kd + LN_EPS);
            }
#pragma unroll
            for (int b4 = 0; b4 < 4; b4++) {
                int i = wid * 8 + half * 4 + b4;
                __half* row = dst + i * SA;
                bool valid = i < ne;
                for (int k = 0; k < NR; k++) {
                    int j = lane + 32 * k;
                    float y = valid ? (xs[b4][k] - mu[b4]) * rstd[b4] * lng[j] + lnb[j] : 0.f;
                    row[j] = __float2half_rn(y);
                }
            }
        }
    };

    auto stage_B = [&](__half* dstB, const __half* wh, int U) {
        for (int idx = tid; idx < 128 * U; idx += 512) {
            int n = idx / U, u = idx - n * U;
            *(uint4*)((char*)dstB + n * SAB + u * 16) =
                ((const uint4*)(wh + (size_t)n * (U * 8)))[u];
        }
    };

    // ---- stage EVERYTHING, then one barrier ----
    stage_ln(true,  aS);
    stage_ln(false, aD);
    stage_B(bK, g_wk_h + (size_t)r * OUT_DIM * CAT_DIM, CAT_DIM / 8);
    stage_B(bV, g_wv_h + (size_t)r * OUT_DIM * CAT_DIM, CAT_DIM / 8);
    stage_B(bQ, g_wq_h + (size_t)r * OUT_DIM * IN_DIM,  IN_DIM / 8);
    __syncthreads();

    // 32x32 warp tile: 4 row-stripes x 4 col-groups
    const int sr = (wid >> 2) * 32;
    const int cg = (wid & 3) * 32;

    const uint32_t aBase = smem_u32(aS) + (uint32_t)(sr + (lane & 15)) * SAB
                         + (uint32_t)(lane >> 4) * 16;
    const int brow = ((lane >> 4) & 1) * 8 + (lane & 7);
    const int bko  = ((lane >> 3) & 1) * 16;
    const uint32_t bBase = smem_u32(sm) + (uint32_t)(cg + brow) * SAB + bko;

    float acc[8][4], kacc[8][4];

    // single-pass product: 4 LDSM + 8 HMMA per k-chunk
    auto run1 = [&](float (*dst)[4], int nk, uint32_t aOff0, uint32_t bOff0) {
        const uint32_t aOff1 = aOff0 + (uint32_t)(16 * SAB);
        const uint32_t bOff1 = bOff0 + (uint32_t)(16 * SAB);
#pragma unroll
        for (int j = 0; j < 8; j++)
#pragma unroll
            for (int b = 0; b < 4; b++) dst[j][b] = 0.f;
#pragma unroll
        for (int ks = 0; ks < 10; ks++) {
            if (ks >= nk) break;
            uint32_t a0[4], a1[4];
            ldsm4(a0[0], a0[1], a0[2], a0[3], aOff0 + ks * 32);
            ldsm4(a1[0], a1[1], a1[2], a1[3], aOff1 + ks * 32);
            uint32_t b0[4], b1[4];
            ldsm4(b0[0], b0[1], b0[2], b0[3], bOff0 + ks * 32);
            ldsm4(b1[0], b1[1], b1[2], b1[3], bOff1 + ks * 32);
#pragma unroll
            for (int rh = 0; rh < 2; rh++) {
                const uint32_t* A = rh ? a1 : a0;
                mma16816(dst[rh * 4 + 0], A, b0[0], b0[1]);
                mma16816(dst[rh * 4 + 1], A, b0[2], b0[3]);
                mma16816(dst[rh * 4 + 2], A, b1[0], b1[1]);
                mma16816(dst[rh * 4 + 3], A, b1[2], b1[3]);
            }
        }
    };

    // ---- K: A_s x Wk ----
    run1(kacc, CAT_DIM / 16, aBase, bBase + 2u * REG);
    // ---- V: A_s x Wv -> g_v ----
    run1(acc,  CAT_DIM / 16, aBase, bBase + 3u * REG);
    {
#pragma unroll
        for (int rh = 0; rh < 2; rh++) {
            int r0 = sr + rh * 16 + (lane >> 2);
            bool vA = r0 < ne, vB = (r0 + 8) < ne;
            size_t gA = vA ? (size_t)so[r0] * OUT_DIM : 0;
            size_t gB = vB ? (size_t)so[r0 + 8] * OUT_DIM : 0;
#pragma unroll
            for (int co = 0; co < 4; co++) {
                int c = cg + co * 8 + (lane & 3) * 2;
                int j = rh * 4 + co;
                if (vA) *(float2*)&g_v[gA + c] = make_float2(acc[j][0], acc[j][1]);
                if (vB) *(float2*)&g_v[gB + c] = make_float2(acc[j][2], acc[j][3]);
            }
        }
    }
    // ---- Q: A_d x Wq ----
    run1(acc, IN_DIM / 16, aBase + (uint32_t)REG, bBase + 4u * REG);

    // ---- logits from fragments: a[e][h] = (q.k)/sqrt(128) ----
    {
#pragma unroll
        for (int rh = 0; rh < 2; rh++) {
            int r0 = sr + rh * 16 + (lane >> 2);
            bool vA = r0 < ne, vB = (r0 + 8) < ne;
#pragma unroll
            for (int hl = 0; hl < 2; hl++) {
                float sA = 0.f, sB = 0.f;
#pragma unroll
                for (int cc = 0; cc < 2; cc++) {
                    int j = rh * 4 + 2 * hl + cc;
                    sA += acc[j][0] * kacc[j][0] + acc[j][1] * kacc[j][1];
                    sB += acc[j][2] * kacc[j][2] + acc[j][3] * kacc[j][3];
                }
                sA += __shfl_xor_sync(0xffffffffu, sA, 1);
                sA += __shfl_xor_sync(0xffffffffu, sA, 2);
                sB += __shfl_xor_sync(0xffffffffu, sB, 1);
                sB += __shfl_xor_sync(0xffffffffu, sB, 2);
                if ((lane & 3) == 0) {
                    int h = (wid & 3) * 2 + hl;
                    if (vA) g_a[(size_t)so[r0] * H_HEADS + h] =
                                sA * 0.08838834764831845f;
                    if (vB) g_a[(size_t)so[r0 + 8] * H_HEADS + h] =
                                sB * 0.08838834764831845f;
                }
            }
        }
    }
}

// ---------------- fused softmax + weighted V (warp per node) ----------
__global__ void k_attn2(int M)
{
    int warp = (blockIdx.x * blockDim.x + threadIdx.x) >> 5;
    int lane = threadIdx.x & 31;
    if (warp >= M) return;
    const int m = warp;
    const int beg = g_doff[m];
    const int cnt = g_dhist[m];
    const int h = lane >> 2;

    float amax = -1e30f, denom = 0.f;
    for (int i = 0; i < cnt; i++) {
        int e = g_dorder[beg + i];
        float a = g_a[(size_t)e * H_HEADS + h];
        float nmax = fmaxf(amax, a);
        denom = denom * __expf(amax - nmax) + __expf(a - nmax);
        amax = nmax;
    }
    float inv = (cnt > 0) ? 1.f / denom : 0.f;

    const int c0 = lane * 4;
    float4 acc = make_float4(0.f, 0.f, 0.f, 0.f);
    for (int i = 0; i < cnt; i++) {
        int e = g_dorder[beg + i];
        float a = g_a[(size_t)e * H_HEADS + h];
        float alpha = __expf(a - amax) * inv;
        float4 v = *(const float4*)&g_v[(size_t)e * OUT_DIM + c0];
        acc.x += v.x * alpha;
        acc.y += v.y * alpha;
        acc.z += v.z * alpha;
        acc.w += v.w * alpha;
    }
    *(float4*)&g_hacc[(size_t)m * OUT_DIM + c0] = acc;
}

// ---------------- typed output projection (tiled by ntype) -------------
__global__ void __launch_bounds__(256, 2)
k_out_t(const float* __restrict__ Wa,
        const float* __restrict__ h_bias,
        const float* __restrict__ skip,
        const float* __restrict__ src_h,
        float* __restrict__ out, int M)
{
    const int r = blockIdx.y;
    const int cnt = g_ncur[r];
    const int tbase = blockIdx.x * TILE_M;
    if (tbase >= cnt) return;
    const size_t base = (size_t)r * M_MAX + tbase;
    const int ne = min(TILE_M, cnt - tbase);

    extern __shared__ float smf[];
    float* Ws = smf;
    float* Ds = smf + OUT_DIM * OUT_DIM;
    const int DS = TILE_M + 4;
    __shared__ int no[TILE_M];

    const int tid = threadIdx.x;
    if (tid < TILE_M) no[tid] = (tid < ne) ? g_norder[base + tid] : 0;
    __syncthreads();

    {
        const float* W = Wa + (size_t)r * OUT_DIM * OUT_DIM;
        for (int idx = tid; idx < OUT_DIM * (OUT_DIM / 4); idx += 256)
            ((float4*)Ws)[idx] = ((const float4*)W)[idx];
    }
    for (int idx = tid; idx < TILE_M * OUT_DIM; idx += 256) {
        int m = idx >> 7;
        int i = idx & 127;
        Ds[i * DS + m] = (m < ne) ?
            g_hacc[(size_t)no[m] * OUT_DIM + i] + h_bias[(size_t)r * OUT_DIM + i] : 0.f;
    }
    __syncthreads();

    const int c0 = (tid & 31) * 4;
    const int m0 = (tid >> 5) * 8;
    ull acc[4][4];
#pragma unroll
    for (int p = 0; p < 4; p++)
#pragma unroll
        for (int b = 0; b < 4; b++) acc[p][b] = 0ull;

#pragma unroll 8
    for (int i = 0; i < OUT_DIM; i++) {
        float4 w = *(const float4*)&Ws[i * OUT_DIM + c0];
        ull wd0 = dup2(w.x), wd1 = dup2(w.y), wd2 = dup2(w.z), wd3 = dup2(w.w);
        ulonglong2 p0 = *(const ulonglong2*)&Ds[i * DS + m0];
        ulonglong2 p1 = *(const ulonglong2*)&Ds[i * DS + m0 + 4];
        ull de[4] = {p0.x, p0.y, p1.x, p1.y};
#pragma unroll
        for (int p = 0; p < 4; p++) {
            acc[p][0] = fma2(de[p], wd0, acc[p][0]);
            acc[p][1] = fma2(de[p], wd1, acc[p][1]);
            acc[p][2] = fma2(de[p], wd2, acc[p][2]);
            acc[p][3] = fma2(de[p], wd3, acc[p][3]);
        }
    }

    float gate = 1.f / (1.f + __expf(-skip[r]));
    float og = 1.f - gate;
#pragma unroll
    for (int p = 0; p < 4; p++) {
        float2 v0 = unpk(acc[p][0]);
        float2 v1 = unpk(acc[p][1]);
        float2 v2 = unpk(acc[p][2]);
        float2 v3 = unpk(acc[p][3]);
        int mA = m0 + 2 * p, mB = mA + 1;
        if (mA < ne) {
            size_t gm = (size_t)no[mA] * OUT_DIM + c0;
            float4 s = *(const float4*)&src_h[gm];
            *(float4*)&out[gm] = make_float4(v0.x * gate + s.x * og,
                                             v1.x * gate + s.y * og,
                                             v2.x * gate + s.z * og,
                                             v3.x * gate + s.w * og);
        }
        if (mB < ne) {
            size_t gm = (size_t)no[mB] * OUT_DIM + c0;
            float4 s = *(const float4*)&src_h[gm];
            *(float4*)&out[gm] = make_float4(v0.y * gate + s.x * og,
                                             v1.y * gate + s.y * og,
                                             v2.y * gate + s.z * og,
                                             v3.y * gate + s.w * og);
        }
    }
}

// ---------------- launch ----------------
extern "C" void kernel_launch(void* const* d_in, const int* in_sizes, int n_in,
                              void* d_out, int out_size)
{
    const float* src_h  = (const float*)d_in[0];
    const float* src_tw = (const float*)d_in[1];
    const float* src_tb = (const float*)d_in[2];
    const float* edge_h = (const float*)d_in[3];
    const float* date   = (const float*)d_in[4];
    const int*   src_idx = (const int*)d_in[5];
    const int*   dst_idx = (const int*)d_in[6];
    const int*   etype   = (const int*)d_in[7];
    const int*   ntype   = (const int*)d_in[8];
    const float* Wq = (const float*)d_in[9];
    const float* Wk = (const float*)d_in[10];
    const float* Wv = (const float*)d_in[11];
    const float* Wa = (const float*)d_in[12];
    const float* h_bias = (const float*)d_in[13];
    const float* skip   = (const float*)d_in[14];
    const float* sg = (const float*)d_in[15];
    const float* sb = (const float*)d_in[16];
    const float* dg = (const float*)d_in[17];
    const float* db = (const float*)d_in[18];
    float* out = (float*)d_out;

    const int E = in_sizes[4];
    const int M = in_sizes[8];

    const int SMF = 5 * REG;  // 215040
    const int SMO = (OUT_DIM * OUT_DIM + OUT_DIM * (TILE_M + 4)) * 4;
    cudaFuncSetAttribute(k_qkv, cudaFuncAttributeMaxDynamicSharedMemorySize, SMF);
    cudaFuncSetAttribute(k_out_t, cudaFuncAttributeMaxDynamicSharedMemorySize, SMO);

    int mx = (E > M) ? E : M;
    {
        dim3 gw((CAT_DIM / 32) * (OUT_DIM / 32), R_TYPES, 3);
        k_wconv2<<<gw, dim3(32, 8)>>>(Wq, Wk, Wv, M);
    }
    k_scatter_all<<<(mx + 255) / 256, 256>>>(etype, ntype, dst_idx, E, M);
    k_scan_dst<<<1, 1024>>>(M);
    k_scatter_dst<<<(E + 255) / 256, 256>>>(dst_idx, E);
    dim3 gq((E + TILE_E - 1) / TILE_E, R_TYPES);
    k_qkv<<<gq, 512, SMF>>>(src_h, src_tw, src_tb, edge_h, date,
                            src_idx, dst_idx, sg, sb, dg, db);
    k_attn2<<<(M * 32 + 255) / 256, 256>>>(M);
    dim3 go((M + TILE_M - 1) / TILE_M, T_TYPES);
    k_out_t<<<go, 256, SMO>>>(Wa, h_bias, skip, src_h, out, M);
}